// round 5
// baseline (speedup 1.0000x reference)
#include <cuda_runtime.h>
#include <cuda_bf16.h>
#include <math.h>

// ---------------------------------------------------------------------------
// Problem constants
// ---------------------------------------------------------------------------
#define H4      4
#define NN      512
#define DIMD    8192
#define ROWS    2048          // H4*NN
#define SEG     4194304       // NN*DIMD elements per (tensor,h)
#define NOUT    128           // inner = heads*dh
#define KSPLIT  8
#define KPER    1024          // 8192 / KSPLIT

// ---------------------------------------------------------------------------
// Device scratch (static allocations only — no cudaMalloc allowed)
// ---------------------------------------------------------------------------
__device__ double g_sum[8];
__device__ double g_sumsq[8];
__device__ float  g_m[8];
__device__ float  g_rinv[8];
__device__ unsigned g_bits[2][ROWS * 256];                 // 4 MB, spike bitmasks
__device__ __nv_bfloat16 g_Whi[2][DIMD * NOUT];            // W hi, layout [o][d]
__device__ __nv_bfloat16 g_Wlo[2][DIMD * NOUT];            // W lo
__device__ float g_Cpart[2 * KSPLIT * ROWS * NOUT];        // 16 MB split-K partials
__device__ float g_out2[NN * 512];                         // (n, h*128+o)
__device__ float g_ic[ROWS * 64];                          // ic values per row
__device__ float g_ipsum[ROWS];
__device__ float g_weff[NN];
__device__ float g_beff;
__device__ float g_o2[NN];
__device__ float g_o3[NN];

// ---------------------------------------------------------------------------
// Helpers
// ---------------------------------------------------------------------------
__device__ __forceinline__ float warp_sum(float v) {
    #pragma unroll
    for (int o = 16; o; o >>= 1) v += __shfl_xor_sync(0xffffffffu, v, o);
    return v;
}
__device__ __forceinline__ float warp_max(float v) {
    #pragma unroll
    for (int o = 16; o; o >>= 1) v = fmaxf(v, __shfl_xor_sync(0xffffffffu, v, o));
    return v;
}

// ---------------------------------------------------------------------------
// K0: zero the double accumulators (graph replays must be deterministic)
// ---------------------------------------------------------------------------
__global__ void k_zero() {
    int t = threadIdx.x;
    if (t < 8) g_sum[t] = 0.0;
    else if (t < 16) g_sumsq[t - 8] = 0.0;
}

// ---------------------------------------------------------------------------
// K1: sum / sumsq per (tensor,h) segment.  grid (2048, 8), 256 thr
// ---------------------------------------------------------------------------
__global__ void k_reduce(const float* __restrict__ pic, const float* __restrict__ ctx) {
    int seg = blockIdx.y;                       // tensor*4 + h
    const float* x = (seg >= 4 ? ctx : pic) + (size_t)(seg & 3) * SEG;
    int base = blockIdx.x * 256 + threadIdx.x;
    float s = 0.f, s2 = 0.f;
    #pragma unroll
    for (int k = 0; k < 8; k++) {
        float v = x[base + k * 524288];
        s += v; s2 += v * v;
    }
    int lane = threadIdx.x & 31, w = threadIdx.x >> 5;
    s = warp_sum(s); s2 = warp_sum(s2);
    __shared__ float aS[8], aS2[8];
    if (lane == 0) { aS[w] = s; aS2[w] = s2; }
    __syncthreads();
    if (threadIdx.x == 0) {
        float ts = 0.f, ts2 = 0.f;
        #pragma unroll
        for (int i = 0; i < 8; i++) { ts += aS[i]; ts2 += aS2[i]; }
        atomicAdd(&g_sum[seg], (double)ts);
        atomicAdd(&g_sumsq[seg], (double)ts2);
    }
}

// ---------------------------------------------------------------------------
// K2: finalize mean / 1/sqrt(var+eps)
// ---------------------------------------------------------------------------
__global__ void k_stats() {
    int t = threadIdx.x;
    if (t < 8) {
        double cnt = (double)SEG;
        double m = g_sum[t] / cnt;
        double v = g_sumsq[t] / cnt - m * m;
        g_m[t] = (float)m;
        g_rinv[t] = (float)(1.0 / sqrt(v + 1e-5));
    }
}

// ---------------------------------------------------------------------------
// K3: spikes -> packed bits.  grid (65536, 2), 256 thr
// ---------------------------------------------------------------------------
__global__ void k_spike(const float* __restrict__ pic, const float* __restrict__ ctx,
                        const float* __restrict__ gamma, const float* __restrict__ beta) {
    int tensor = blockIdx.y;
    int idx = blockIdx.x * 256 + threadIdx.x;
    const float* x = tensor ? ctx : pic;
    int h = idx >> 22;          // / SEG
    int d = idx & (DIMD - 1);
    float m = g_m[tensor * 4 + h];
    float rinv = g_rinv[tensor * 4 + h];
    float y = (x[idx] - m) * rinv;
    bool sp = (__fadd_rn(__fmul_rn(y, gamma[d]), beta[d]) > 1.0f);
    unsigned ball = __ballot_sync(0xffffffffu, sp);
    if ((threadIdx.x & 31) == 0) g_bits[tensor][idx >> 5] = ball;
}

// ---------------------------------------------------------------------------
// K4: W -> bf16 hi/lo split (exact to ~16 mantissa bits).  grid (4096, 2), 256 thr
// ---------------------------------------------------------------------------
__global__ void k_prepW(const float* __restrict__ Wpic, const float* __restrict__ Wctx) {
    int mat = blockIdx.y;
    int i = blockIdx.x * 256 + threadIdx.x;     // 0 .. 1048575, layout [o][d]
    const float* W = mat ? Wctx : Wpic;
    float w = W[i];
    __nv_bfloat16 hi = __float2bfloat16(w);
    __nv_bfloat16 lo = __float2bfloat16(w - __bfloat162float(hi));
    g_Whi[mat][i] = hi;
    g_Wlo[mat][i] = lo;
}

// ---------------------------------------------------------------------------
// K5: GEMM  C[row][o] = sum_d spike[row][d] * W[o][d]
//     A from bits, B = Whi + Wlo (bf16), fp32 accum, mma.sync m16n8k16.
//     BM=64, BN=128, BK=64. grid (32, KSPLIT, 2), 256 thr (8 warps: 4m x 2n)
// ---------------------------------------------------------------------------
__global__ void __launch_bounds__(256) k_gemm() {
    __shared__ __align__(16) __nv_bfloat16 As[64 * 72];
    __shared__ __align__(16) __nv_bfloat16 Bh[128 * 72];
    __shared__ __align__(16) __nv_bfloat16 Bl[128 * 72];

    int tid = threadIdx.x;
    int mt = blockIdx.x, kz = blockIdx.y, mat = blockIdx.z;
    int mbase = mt * 64;
    const unsigned* bits = g_bits[mat];
    const unsigned* Whi32 = (const unsigned*)g_Whi[mat];
    const unsigned* Wlo32 = (const unsigned*)g_Wlo[mat];

    int lane = tid & 31, w = tid >> 5;
    int wm = w >> 1, wn = w & 1;
    int gid = lane >> 2, tig = lane & 3;

    float acc[8][4];
    #pragma unroll
    for (int i = 0; i < 8; i++)
        #pragma unroll
        for (int j = 0; j < 4; j++) acc[i][j] = 0.f;

    int r_fill = tid >> 2, q = tid & 3;

    for (int kb = 0; kb < KPER / 64; kb++) {
        int k0 = kz * KPER + kb * 64;
        // ---- A tile from bits: 64 rows x 64 k, as bf16 0/1 ----
        {
            unsigned word = bits[(mbase + r_fill) * 256 + (k0 >> 5) + (q >> 1)];
            unsigned b16 = (word >> (16 * (q & 1))) & 0xffffu;
            #pragma unroll
            for (int j = 0; j < 8; j++) {
                unsigned lo = ((b16 >> (2 * j)) & 1u) ? 0x3F80u : 0u;
                unsigned hi = ((b16 >> (2 * j + 1)) & 1u) ? 0x3F80u : 0u;
                *(unsigned*)&As[r_fill * 72 + q * 16 + 2 * j] = lo | (hi << 16);
            }
        }
        // ---- B tiles (hi & lo): 128 n-rows x 64 k ----
        #pragma unroll
        for (int i = 0; i < 16; i++) {
            int l = i * 256 + tid;
            int o = l >> 5, du = l & 31;
            *(unsigned*)&Bh[o * 72 + du * 2] = Whi32[o * 4096 + (k0 >> 1) + du];
            *(unsigned*)&Bl[o * 72 + du * 2] = Wlo32[o * 4096 + (k0 >> 1) + du];
        }
        __syncthreads();

        #pragma unroll
        for (int ks = 0; ks < 64; ks += 16) {
            int r0 = wm * 16 + gid;
            int c  = ks + tig * 2;
            unsigned a0 = *(const unsigned*)&As[r0 * 72 + c];
            unsigned a1 = *(const unsigned*)&As[(r0 + 8) * 72 + c];
            unsigned a2 = *(const unsigned*)&As[r0 * 72 + c + 8];
            unsigned a3 = *(const unsigned*)&As[(r0 + 8) * 72 + c + 8];
            #pragma unroll
            for (int nt = 0; nt < 8; nt++) {
                int nb = (wn * 64 + nt * 8 + gid) * 72;
                unsigned b0 = *(const unsigned*)&Bh[nb + c];
                unsigned b1 = *(const unsigned*)&Bh[nb + c + 8];
                asm volatile(
                    "mma.sync.aligned.m16n8k16.row.col.f32.bf16.bf16.f32 "
                    "{%0,%1,%2,%3}, {%4,%5,%6,%7}, {%8,%9}, {%0,%1,%2,%3};\n"
                    : "+f"(acc[nt][0]), "+f"(acc[nt][1]), "+f"(acc[nt][2]), "+f"(acc[nt][3])
                    : "r"(a0), "r"(a1), "r"(a2), "r"(a3), "r"(b0), "r"(b1));
                unsigned d0 = *(const unsigned*)&Bl[nb + c];
                unsigned d1 = *(const unsigned*)&Bl[nb + c + 8];
                asm volatile(
                    "mma.sync.aligned.m16n8k16.row.col.f32.bf16.bf16.f32 "
                    "{%0,%1,%2,%3}, {%4,%5,%6,%7}, {%8,%9}, {%0,%1,%2,%3};\n"
                    : "+f"(acc[nt][0]), "+f"(acc[nt][1]), "+f"(acc[nt][2]), "+f"(acc[nt][3])
                    : "r"(a0), "r"(a1), "r"(a2), "r"(a3), "r"(d0), "r"(d1));
            }
        }
        __syncthreads();
    }

    // ---- store split-K partials ----
    int part = mat * KSPLIT + kz;
    #pragma unroll
    for (int nt = 0; nt < 8; nt++) {
        int col = wn * 64 + nt * 8 + tig * 2;
        int row0 = mbase + wm * 16 + gid;
        size_t i0 = ((size_t)(part * ROWS + row0)) * NOUT + col;
        g_Cpart[i0]     = acc[nt][0];
        g_Cpart[i0 + 1] = acc[nt][1];
        size_t i1 = i0 + (size_t)8 * NOUT;
        g_Cpart[i1]     = acc[nt][2];
        g_Cpart[i1 + 1] = acc[nt][3];
    }
}

// ---------------------------------------------------------------------------
// K6: per-row epilogue: bias, scale, s_ic/s_V, softmax, out2 / ic / ip_sum.
//     grid 2048 blocks (row = h*512+n), 128 thr (o)
// ---------------------------------------------------------------------------
__global__ void k_epilogue(const float* __restrict__ b_pic, const float* __restrict__ b_ctx) {
    int row = blockIdx.x;
    int o = threadIdx.x;
    int lane = o & 31, w = o >> 5;

    float ipv = b_pic[o];
    #pragma unroll
    for (int s = 0; s < KSPLIT; s++)
        ipv += g_Cpart[((size_t)(s * ROWS + row)) * NOUT + o];
    ipv *= 0.125f;                                  // SCALE = 64^-0.5

    float ctxv = b_ctx[o];
    #pragma unroll
    for (int s = 0; s < KSPLIT; s++)
        ctxv += g_Cpart[((size_t)((KSPLIT + s) * ROWS + row)) * NOUT + o];

    __shared__ float sA[4], sB[4], sM[4], sZ[4];
    float cs = warp_sum(ctxv);
    float is = warp_sum(ipv);
    if (lane == 0) { sA[w] = cs; sB[w] = is; }
    __syncthreads();
    float s_ic = sA[0] + sA[1];                     // o < 64  -> warps 0,1
    float s_V  = sA[2] + sA[3];                     // o >= 64 -> warps 2,3
    float ipsum = sB[0] + sB[1] + sB[2] + sB[3];

    float sim = ipv * s_ic;
    float mw = warp_max(sim);
    if (lane == 0) sM[w] = mw;
    __syncthreads();
    float mx = fmaxf(fmaxf(sM[0], sM[1]), fmaxf(sM[2], sM[3]));
    float e = expf(sim - mx);
    float zw = warp_sum(e);
    if (lane == 0) sZ[w] = zw;
    __syncthreads();
    float Z = sZ[0] + sZ[1] + sZ[2] + sZ[3];
    float outv = (e / Z) * s_V;

    int h = row >> 9, n = row & 511;
    g_out2[n * 512 + h * 128 + o] = outv;
    if (o < 64) g_ic[row * 64 + o] = ctxv;
    if (o == 0) g_ipsum[row] = ipsum;
}

// ---------------------------------------------------------------------------
// K7: fuse conv1 (32x512) and conv2 (1x32) into a single 512-vector
// ---------------------------------------------------------------------------
__global__ void k_head1(const float* __restrict__ c1w, const float* __restrict__ c1b,
                        const float* __restrict__ c2w, const float* __restrict__ c2b) {
    int c = threadIdx.x;                // 512 threads
    float acc = 0.f;
    #pragma unroll
    for (int o = 0; o < 32; o++) acc += c2w[o] * c1w[o * 512 + c];
    g_weff[c] = acc;
    if (c == 0) {
        float b = 0.f;
        #pragma unroll
        for (int o = 0; o < 32; o++) b += c2w[o] * c1b[o];
        g_beff = b + c2b[0];
    }
}

// K8: o2[l] = sum_c w_eff[c]*out2[c][l] + b_eff.  grid 2 x 256 thr
__global__ void k_head2() {
    int l = blockIdx.x * 256 + threadIdx.x;
    float acc = g_beff;
    for (int c = 0; c < 512; c++) acc += g_weff[c] * g_out2[c * 512 + l];
    g_o2[l] = acc;
}

// K9: o3[j] = o2 . fc_w[j,:] + fc_b[j].  grid 512 blocks x 128 thr
__global__ void k_head3(const float* __restrict__ fcw, const float* __restrict__ fcb) {
    int j = blockIdx.x;
    int t = threadIdx.x, lane = t & 31, w = t >> 5;
    float p = 0.f;
    for (int l = t; l < 512; l += 128) p += g_o2[l] * fcw[j * 512 + l];
    p = warp_sum(p);
    __shared__ float sP[4];
    if (lane == 0) sP[w] = p;
    __syncthreads();
    if (t == 0) g_o3[j] = sP[0] + sP[1] + sP[2] + sP[3] + fcb[j];
}

// ---------------------------------------------------------------------------
// K10: final — broadcast add, transpose, 4->64 linear interp, relus + ic_sum
//      grid 512 blocks (n) x 64 thr (j)
// ---------------------------------------------------------------------------
__global__ void k_final(float* __restrict__ out) {
    int n = blockIdx.x, j = threadIdx.x;
    float o3n = g_o3[n];
    float tv[4];
    #pragma unroll
    for (int h = 0; h < 4; h++) tv[h] = o3n + g_ipsum[h * 512 + n];
    float src = fmaxf((j + 0.5f) * 0.0625f - 0.5f, 0.0f);
    int i0 = (int)floorf(src); if (i0 > 3) i0 = 3;
    int i1 = i0 + 1; if (i1 > 3) i1 = 3;
    float wgt = src - (float)i0;
    float val = tv[i0] * (1.0f - wgt) + tv[i1] * wgt;
    val = fmaxf(val, 0.0f);
    float ics = 0.f;
    #pragma unroll
    for (int h = 0; h < 4; h++) ics += g_ic[(h * 512 + n) * 64 + j];
    out[n * 64 + j] = fmaxf(val + ics, 0.0f);
}

// ---------------------------------------------------------------------------
// Launch
// ---------------------------------------------------------------------------
extern "C" void kernel_launch(void* const* d_in, const int* in_sizes, int n_in,
                              void* d_out, int out_size) {
    const float* pic    = (const float*)d_in[0];
    const float* ctx    = (const float*)d_in[1];
    const float* gamma  = (const float*)d_in[2];
    const float* lnbeta = (const float*)d_in[3];
    const float* Wpic   = (const float*)d_in[4];
    const float* bpic   = (const float*)d_in[5];
    const float* Wctx   = (const float*)d_in[6];
    const float* bctx   = (const float*)d_in[7];
    const float* c1w    = (const float*)d_in[8];
    const float* c1b    = (const float*)d_in[9];
    const float* c2w    = (const float*)d_in[10];
    const float* c2b    = (const float*)d_in[11];
    const float* fcw    = (const float*)d_in[12];
    const float* fcb    = (const float*)d_in[13];
    float* out = (float*)d_out;

    k_zero<<<1, 32>>>();
    k_reduce<<<dim3(2048, 8), 256>>>(pic, ctx);
    k_stats<<<1, 32>>>();
    k_spike<<<dim3(65536, 2), 256>>>(pic, ctx, gamma, lnbeta);
    k_prepW<<<dim3(4096, 2), 256>>>(Wpic, Wctx);
    k_gemm<<<dim3(32, KSPLIT, 2), 256>>>();
    k_epilogue<<<ROWS, 128>>>(bpic, bctx);
    k_head1<<<1, 512>>>(c1w, c1b, c2w, c2b);
    k_head2<<<2, 256>>>();
    k_head3<<<512, 128>>>(fcw, fcb);
    k_final<<<512, 64>>>(out);
}

// round 7
// speedup vs baseline: 1.0353x; 1.0353x over previous
#include <cuda_runtime.h>
#include <cuda_bf16.h>
#include <math.h>

// ---------------------------------------------------------------------------
// Problem constants
// ---------------------------------------------------------------------------
#define H4      4
#define NN      512
#define DIMD    8192
#define ROWS    2048          // H4*NN
#define SEG     4194304       // NN*DIMD elements per (tensor,h)
#define NOUT    128           // inner = heads*dh
#define KSPLIT  8
#define KPER    1024          // 8192 / KSPLIT

// ---------------------------------------------------------------------------
// Device scratch (static allocations only — no cudaMalloc allowed)
// ---------------------------------------------------------------------------
__device__ double g_sum[8];
__device__ double g_sumsq[8];
__device__ float  g_m[8];
__device__ float  g_rinv[8];
__device__ unsigned g_bits[2][ROWS * 256];                 // 4 MB, spike bitmasks
__device__ __nv_bfloat16 g_Whi[2][DIMD * NOUT];            // W hi, layout [o][d]
__device__ __nv_bfloat16 g_Wlo[2][DIMD * NOUT];            // W lo
__device__ float g_Cpart[2 * KSPLIT * ROWS * NOUT];        // 16 MB split-K partials
__device__ float g_out2[NN * 512];                         // (n, h*128+o)
__device__ float g_ic[ROWS * 64];                          // ic values per row
__device__ float g_ipsum[ROWS];
__device__ float g_weff[NN];
__device__ float g_beff;
__device__ float g_o2[NN];
__device__ float g_o3[NN];

// ---------------------------------------------------------------------------
// Helpers
// ---------------------------------------------------------------------------
__device__ __forceinline__ float warp_sum(float v) {
    #pragma unroll
    for (int o = 16; o; o >>= 1) v += __shfl_xor_sync(0xffffffffu, v, o);
    return v;
}
__device__ __forceinline__ float warp_max(float v) {
    #pragma unroll
    for (int o = 16; o; o >>= 1) v = fmaxf(v, __shfl_xor_sync(0xffffffffu, v, o));
    return v;
}

// ---------------------------------------------------------------------------
// K0: zero the double accumulators (graph replays must be deterministic)
// ---------------------------------------------------------------------------
__global__ void k_zero() {
    int t = threadIdx.x;
    if (t < 8) g_sum[t] = 0.0;
    else if (t < 16) g_sumsq[t - 8] = 0.0;
}

// ---------------------------------------------------------------------------
// K1: sum / sumsq per (tensor,h) segment.  grid (1024, 8), 256 thr, float4
// ---------------------------------------------------------------------------
__global__ void k_reduce(const float* __restrict__ pic, const float* __restrict__ ctx) {
    int seg = blockIdx.y;                       // tensor*4 + h
    const float4* x = (const float4*)((seg >= 4 ? ctx : pic) + (size_t)(seg & 3) * SEG);
    int base = blockIdx.x * 256 + threadIdx.x;  // float4 index, 0..262143 per step
    float s = 0.f, s2 = 0.f;
    #pragma unroll
    for (int k = 0; k < 4; k++) {
        float4 v = x[base + k * 262144];
        s  += (v.x + v.y) + (v.z + v.w);
        s2 += (v.x * v.x + v.y * v.y) + (v.z * v.z + v.w * v.w);
    }
    int lane = threadIdx.x & 31, w = threadIdx.x >> 5;
    s = warp_sum(s); s2 = warp_sum(s2);
    __shared__ float aS[8], aS2[8];
    if (lane == 0) { aS[w] = s; aS2[w] = s2; }
    __syncthreads();
    if (threadIdx.x == 0) {
        float ts = 0.f, ts2 = 0.f;
        #pragma unroll
        for (int i = 0; i < 8; i++) { ts += aS[i]; ts2 += aS2[i]; }
        atomicAdd(&g_sum[seg], (double)ts);
        atomicAdd(&g_sumsq[seg], (double)ts2);
    }
}

// ---------------------------------------------------------------------------
// K2: finalize mean / 1/sqrt(var+eps)
// ---------------------------------------------------------------------------
__global__ void k_stats() {
    int t = threadIdx.x;
    if (t < 8) {
        double cnt = (double)SEG;
        double m = g_sum[t] / cnt;
        double v = g_sumsq[t] / cnt - m * m;
        g_m[t] = (float)m;
        g_rinv[t] = (float)(1.0 / sqrt(v + 1e-5));
    }
}

// ---------------------------------------------------------------------------
// K3: spikes -> packed bits. One thread produces one 32-bit word.
//     words per tensor = 4*SEG/32 = 524288  ->  grid (2048, 2), 256 thr.
//     8x float4 loads per thread (128B), no ballot.
//     Arithmetic sequence identical to the R4 passing version.
// ---------------------------------------------------------------------------
__global__ void k_spike(const float* __restrict__ pic, const float* __restrict__ ctx,
                        const float* __restrict__ gamma, const float* __restrict__ beta) {
    int tensor = blockIdx.y;
    int wIdx = blockIdx.x * 256 + threadIdx.x;      // word index 0..524287
    const float4* x = (const float4*)(tensor ? ctx : pic);
    int h = wIdx >> 17;                             // word covers 32 elems; / (SEG/32)
    float m = g_m[tensor * 4 + h];
    float rinv = g_rinv[tensor * 4 + h];
    int d0 = (wIdx * 32) & (DIMD - 1);              // 32-aligned within DIM
    unsigned word = 0;
    #pragma unroll
    for (int j = 0; j < 8; j++) {
        float4 v = x[wIdx * 8 + j];
        float4 ga = *(const float4*)&gamma[d0 + j * 4];
        float4 be = *(const float4*)&beta[d0 + j * 4];
        float y0 = (v.x - m) * rinv;
        float y1 = (v.y - m) * rinv;
        float y2 = (v.z - m) * rinv;
        float y3 = (v.w - m) * rinv;
        unsigned b = 0;
        b |= (__fadd_rn(__fmul_rn(y0, ga.x), be.x) > 1.0f) ? 1u : 0u;
        b |= (__fadd_rn(__fmul_rn(y1, ga.y), be.y) > 1.0f) ? 2u : 0u;
        b |= (__fadd_rn(__fmul_rn(y2, ga.z), be.z) > 1.0f) ? 4u : 0u;
        b |= (__fadd_rn(__fmul_rn(y3, ga.w), be.w) > 1.0f) ? 8u : 0u;
        word |= b << (4 * j);
    }
    g_bits[tensor][wIdx] = word;
}

// ---------------------------------------------------------------------------
// K4: W -> bf16 hi/lo split.  float4 in, packed unsigned out.
//     grid (1024, 2), 256 thr
// ---------------------------------------------------------------------------
__global__ void k_prepW(const float* __restrict__ Wpic, const float* __restrict__ Wctx) {
    int mat = blockIdx.y;
    int i = blockIdx.x * 256 + threadIdx.x;     // float4 index 0..262143
    const float4* W = (const float4*)(mat ? Wctx : Wpic);
    float4 wv = W[i];
    unsigned* Whi32 = (unsigned*)g_Whi[mat];
    unsigned* Wlo32 = (unsigned*)g_Wlo[mat];
    __nv_bfloat16 h0 = __float2bfloat16(wv.x), h1 = __float2bfloat16(wv.y);
    __nv_bfloat16 h2 = __float2bfloat16(wv.z), h3 = __float2bfloat16(wv.w);
    __nv_bfloat16 l0 = __float2bfloat16(wv.x - __bfloat162float(h0));
    __nv_bfloat16 l1 = __float2bfloat16(wv.y - __bfloat162float(h1));
    __nv_bfloat16 l2 = __float2bfloat16(wv.z - __bfloat162float(h2));
    __nv_bfloat16 l3 = __float2bfloat16(wv.w - __bfloat162float(h3));
    unsigned hi01 = (unsigned)*(unsigned short*)&h0 | ((unsigned)*(unsigned short*)&h1 << 16);
    unsigned hi23 = (unsigned)*(unsigned short*)&h2 | ((unsigned)*(unsigned short*)&h3 << 16);
    unsigned lo01 = (unsigned)*(unsigned short*)&l0 | ((unsigned)*(unsigned short*)&l1 << 16);
    unsigned lo23 = (unsigned)*(unsigned short*)&l2 | ((unsigned)*(unsigned short*)&l3 << 16);
    Whi32[i * 2] = hi01; Whi32[i * 2 + 1] = hi23;
    Wlo32[i * 2] = lo01; Wlo32[i * 2 + 1] = lo23;
}

// ---------------------------------------------------------------------------
// K5: GEMM  C[row][o] = sum_d spike[row][d] * W[o][d]
//     A from bits, B = Whi + Wlo (bf16), fp32 accum, mma.sync m16n8k16.
//     BM=64, BN=128, BK=64. grid (32, KSPLIT, 2), 256 thr (8 warps: 4m x 2n)
// ---------------------------------------------------------------------------
__global__ void __launch_bounds__(256) k_gemm() {
    __shared__ __align__(16) __nv_bfloat16 As[64 * 72];
    __shared__ __align__(16) __nv_bfloat16 Bh[128 * 72];
    __shared__ __align__(16) __nv_bfloat16 Bl[128 * 72];

    int tid = threadIdx.x;
    int mt = blockIdx.x, kz = blockIdx.y, mat = blockIdx.z;
    int mbase = mt * 64;
    const unsigned* bits = g_bits[mat];
    const unsigned* Whi32 = (const unsigned*)g_Whi[mat];
    const unsigned* Wlo32 = (const unsigned*)g_Wlo[mat];

    int lane = tid & 31, w = tid >> 5;
    int wm = w >> 1, wn = w & 1;
    int gid = lane >> 2, tig = lane & 3;

    float acc[8][4];
    #pragma unroll
    for (int i = 0; i < 8; i++)
        #pragma unroll
        for (int j = 0; j < 4; j++) acc[i][j] = 0.f;

    int r_fill = tid >> 2, q = tid & 3;

    for (int kb = 0; kb < KPER / 64; kb++) {
        int k0 = kz * KPER + kb * 64;
        // ---- A tile from bits: 64 rows x 64 k, as bf16 0/1 ----
        {
            unsigned word = bits[(mbase + r_fill) * 256 + (k0 >> 5) + (q >> 1)];
            unsigned b16 = (word >> (16 * (q & 1))) & 0xffffu;
            #pragma unroll
            for (int j = 0; j < 8; j++) {
                unsigned lo = ((b16 >> (2 * j)) & 1u) ? 0x3F80u : 0u;
                unsigned hi = ((b16 >> (2 * j + 1)) & 1u) ? 0x3F80u : 0u;
                *(unsigned*)&As[r_fill * 72 + q * 16 + 2 * j] = lo | (hi << 16);
            }
        }
        // ---- B tiles (hi & lo): 128 n-rows x 64 k ----
        #pragma unroll
        for (int i = 0; i < 16; i++) {
            int l = i * 256 + tid;
            int o = l >> 5, du = l & 31;
            *(unsigned*)&Bh[o * 72 + du * 2] = Whi32[o * 4096 + (k0 >> 1) + du];
            *(unsigned*)&Bl[o * 72 + du * 2] = Wlo32[o * 4096 + (k0 >> 1) + du];
        }
        __syncthreads();

        #pragma unroll
        for (int ks = 0; ks < 64; ks += 16) {
            int r0 = wm * 16 + gid;
            int c  = ks + tig * 2;
            unsigned a0 = *(const unsigned*)&As[r0 * 72 + c];
            unsigned a1 = *(const unsigned*)&As[(r0 + 8) * 72 + c];
            unsigned a2 = *(const unsigned*)&As[r0 * 72 + c + 8];
            unsigned a3 = *(const unsigned*)&As[(r0 + 8) * 72 + c + 8];
            #pragma unroll
            for (int nt = 0; nt < 8; nt++) {
                int nb = (wn * 64 + nt * 8 + gid) * 72;
                unsigned b0 = *(const unsigned*)&Bh[nb + c];
                unsigned b1 = *(const unsigned*)&Bh[nb + c + 8];
                asm volatile(
                    "mma.sync.aligned.m16n8k16.row.col.f32.bf16.bf16.f32 "
                    "{%0,%1,%2,%3}, {%4,%5,%6,%7}, {%8,%9}, {%0,%1,%2,%3};\n"
                    : "+f"(acc[nt][0]), "+f"(acc[nt][1]), "+f"(acc[nt][2]), "+f"(acc[nt][3])
                    : "r"(a0), "r"(a1), "r"(a2), "r"(a3), "r"(b0), "r"(b1));
                unsigned d0 = *(const unsigned*)&Bl[nb + c];
                unsigned d1 = *(const unsigned*)&Bl[nb + c + 8];
                asm volatile(
                    "mma.sync.aligned.m16n8k16.row.col.f32.bf16.bf16.f32 "
                    "{%0,%1,%2,%3}, {%4,%5,%6,%7}, {%8,%9}, {%0,%1,%2,%3};\n"
                    : "+f"(acc[nt][0]), "+f"(acc[nt][1]), "+f"(acc[nt][2]), "+f"(acc[nt][3])
                    : "r"(a0), "r"(a1), "r"(a2), "r"(a3), "r"(d0), "r"(d1));
            }
        }
        __syncthreads();
    }

    // ---- store split-K partials ----
    int part = mat * KSPLIT + kz;
    #pragma unroll
    for (int nt = 0; nt < 8; nt++) {
        int col = wn * 64 + nt * 8 + tig * 2;
        int row0 = mbase + wm * 16 + gid;
        size_t i0 = ((size_t)(part * ROWS + row0)) * NOUT + col;
        g_Cpart[i0]     = acc[nt][0];
        g_Cpart[i0 + 1] = acc[nt][1];
        size_t i1 = i0 + (size_t)8 * NOUT;
        g_Cpart[i1]     = acc[nt][2];
        g_Cpart[i1 + 1] = acc[nt][3];
    }
}

// ---------------------------------------------------------------------------
// K6: per-row epilogue: bias, scale, s_ic/s_V, softmax, out2 / ic / ip_sum.
//     grid 2048 blocks (row = h*512+n), 128 thr (o)
// ---------------------------------------------------------------------------
__global__ void k_epilogue(const float* __restrict__ b_pic, const float* __restrict__ b_ctx) {
    int row = blockIdx.x;
    int o = threadIdx.x;
    int lane = o & 31, w = o >> 5;

    float ipv = b_pic[o];
    #pragma unroll
    for (int s = 0; s < KSPLIT; s++)
        ipv += g_Cpart[((size_t)(s * ROWS + row)) * NOUT + o];
    ipv *= 0.125f;                                  // SCALE = 64^-0.5

    float ctxv = b_ctx[o];
    #pragma unroll
    for (int s = 0; s < KSPLIT; s++)
        ctxv += g_Cpart[((size_t)((KSPLIT + s) * ROWS + row)) * NOUT + o];

    __shared__ float sA[4], sB[4], sM[4], sZ[4];
    float cs = warp_sum(ctxv);
    float is = warp_sum(ipv);
    if (lane == 0) { sA[w] = cs; sB[w] = is; }
    __syncthreads();
    float s_ic = sA[0] + sA[1];                     // o < 64  -> warps 0,1
    float s_V  = sA[2] + sA[3];                     // o >= 64 -> warps 2,3
    float ipsum = sB[0] + sB[1] + sB[2] + sB[3];

    float sim = ipv * s_ic;
    float mw = warp_max(sim);
    if (lane == 0) sM[w] = mw;
    __syncthreads();
    float mx = fmaxf(fmaxf(sM[0], sM[1]), fmaxf(sM[2], sM[3]));
    float e = expf(sim - mx);
    float zw = warp_sum(e);
    if (lane == 0) sZ[w] = zw;
    __syncthreads();
    float Z = sZ[0] + sZ[1] + sZ[2] + sZ[3];
    float outv = (e / Z) * s_V;

    int h = row >> 9, n = row & 511;
    g_out2[n * 512 + h * 128 + o] = outv;
    if (o < 64) g_ic[row * 64 + o] = ctxv;
    if (o == 0) g_ipsum[row] = ipsum;
}

// ---------------------------------------------------------------------------
// K7: fuse conv1 (32x512) and conv2 (1x32) into a single 512-vector
// ---------------------------------------------------------------------------
__global__ void k_head1(const float* __restrict__ c1w, const float* __restrict__ c1b,
                        const float* __restrict__ c2w, const float* __restrict__ c2b) {
    int c = threadIdx.x;                // 512 threads
    float acc = 0.f;
    #pragma unroll
    for (int o = 0; o < 32; o++) acc += c2w[o] * c1w[o * 512 + c];
    g_weff[c] = acc;
    if (c == 0) {
        float b = 0.f;
        #pragma unroll
        for (int o = 0; o < 32; o++) b += c2w[o] * c1b[o];
        g_beff = b + c2b[0];
    }
}

// K8: o2[l] = sum_c w_eff[c]*out2[c][l] + b_eff.  grid 2 x 256 thr
__global__ void k_head2() {
    int l = blockIdx.x * 256 + threadIdx.x;
    float acc = g_beff;
    for (int c = 0; c < 512; c++) acc += g_weff[c] * g_out2[c * 512 + l];
    g_o2[l] = acc;
}

// K9: o3[j] = o2 . fc_w[j,:] + fc_b[j].  grid 512 blocks x 128 thr
__global__ void k_head3(const float* __restrict__ fcw, const float* __restrict__ fcb) {
    int j = blockIdx.x;
    int t = threadIdx.x, lane = t & 31, w = t >> 5;
    float p = 0.f;
    for (int l = t; l < 512; l += 128) p += g_o2[l] * fcw[j * 512 + l];
    p = warp_sum(p);
    __shared__ float sP[4];
    if (lane == 0) sP[w] = p;
    __syncthreads();
    if (t == 0) g_o3[j] = sP[0] + sP[1] + sP[2] + sP[3] + fcb[j];
}

// ---------------------------------------------------------------------------
// K10: final — broadcast add, transpose, 4->64 linear interp, relus + ic_sum
//      grid 512 blocks (n) x 64 thr (j)
// ---------------------------------------------------------------------------
__global__ void k_final(float* __restrict__ out) {
    int n = blockIdx.x, j = threadIdx.x;
    float o3n = g_o3[n];
    float tv[4];
    #pragma unroll
    for (int h = 0; h < 4; h++) tv[h] = o3n + g_ipsum[h * 512 + n];
    float src = fmaxf((j + 0.5f) * 0.0625f - 0.5f, 0.0f);
    int i0 = (int)floorf(src); if (i0 > 3) i0 = 3;
    int i1 = i0 + 1; if (i1 > 3) i1 = 3;
    float wgt = src - (float)i0;
    float val = tv[i0] * (1.0f - wgt) + tv[i1] * wgt;
    val = fmaxf(val, 0.0f);
    float ics = 0.f;
    #pragma unroll
    for (int h = 0; h < 4; h++) ics += g_ic[(h * 512 + n) * 64 + j];
    out[n * 64 + j] = fmaxf(val + ics, 0.0f);
}

// ---------------------------------------------------------------------------
// Launch
// ---------------------------------------------------------------------------
extern "C" void kernel_launch(void* const* d_in, const int* in_sizes, int n_in,
                              void* d_out, int out_size) {
    const float* pic    = (const float*)d_in[0];
    const float* ctx    = (const float*)d_in[1];
    const float* gamma  = (const float*)d_in[2];
    const float* lnbeta = (const float*)d_in[3];
    const float* Wpic   = (const float*)d_in[4];
    const float* bpic   = (const float*)d_in[5];
    const float* Wctx   = (const float*)d_in[6];
    const float* bctx   = (const float*)d_in[7];
    const float* c1w    = (const float*)d_in[8];
    const float* c1b    = (const float*)d_in[9];
    const float* c2w    = (const float*)d_in[10];
    const float* c2b    = (const float*)d_in[11];
    const float* fcw    = (const float*)d_in[12];
    const float* fcb    = (const float*)d_in[13];
    float* out = (float*)d_out;

    k_zero<<<1, 32>>>();
    k_reduce<<<dim3(1024, 8), 256>>>(pic, ctx);
    k_stats<<<1, 32>>>();
    k_spike<<<dim3(2048, 2), 256>>>(pic, ctx, gamma, lnbeta);
    k_prepW<<<dim3(1024, 2), 256>>>(Wpic, Wctx);
    k_gemm<<<dim3(32, KSPLIT, 2), 256>>>();
    k_epilogue<<<ROWS, 128>>>(bpic, bctx);
    k_head1<<<1, 512>>>(c1w, c1b, c2w, c2b);
    k_head2<<<2, 256>>>();
    k_head3<<<512, 128>>>(fcw, fcb);
    k_final<<<512, 64>>>(out);
}

// round 8
// speedup vs baseline: 1.3325x; 1.2871x over previous
#include <cuda_runtime.h>
#include <cuda_bf16.h>
#include <math.h>

// ---------------------------------------------------------------------------
// Problem constants
// ---------------------------------------------------------------------------
#define H4      4
#define NN      512
#define DIMD    8192
#define ROWS    2048          // H4*NN
#define SEG     4194304       // NN*DIMD elements per (tensor,h)
#define NOUT    128           // inner = heads*dh
#define KSPLIT  8
#define KPER    1024          // 8192 / KSPLIT

// ---------------------------------------------------------------------------
// Device scratch (static allocations only — no cudaMalloc allowed)
// ---------------------------------------------------------------------------
__device__ double g_sum[8];
__device__ double g_sumsq[8];
__device__ float  g_m[8];
__device__ float  g_rinv[8];
__device__ unsigned g_bits[2][ROWS * 256];                 // 4 MB, spike bitmasks
__device__ __nv_bfloat16 g_Whi[2][DIMD * NOUT];            // W hi, layout [o][d]
__device__ __nv_bfloat16 g_Wlo[2][DIMD * NOUT];            // W lo
__device__ float g_Cpart[2 * KSPLIT * ROWS * NOUT];        // 16 MB split-K partials
__device__ float g_out2[NN * 512];                         // (n, h*128+o)
__device__ float g_ic[ROWS * 64];                          // ic values per row
__device__ float g_ipsum[ROWS];
__device__ float g_weff[NN];
__device__ float g_beff;
__device__ float g_o2[NN];
__device__ float g_o3[NN];

// ---------------------------------------------------------------------------
// Helpers
// ---------------------------------------------------------------------------
__device__ __forceinline__ float warp_sum(float v) {
    #pragma unroll
    for (int o = 16; o; o >>= 1) v += __shfl_xor_sync(0xffffffffu, v, o);
    return v;
}
__device__ __forceinline__ float warp_max(float v) {
    #pragma unroll
    for (int o = 16; o; o >>= 1) v = fmaxf(v, __shfl_xor_sync(0xffffffffu, v, o));
    return v;
}

// ---------------------------------------------------------------------------
// K0: zero the double accumulators (graph replays must be deterministic)
// ---------------------------------------------------------------------------
__global__ void k_zero() {
    int t = threadIdx.x;
    if (t < 8) g_sum[t] = 0.0;
    else if (t < 16) g_sumsq[t - 8] = 0.0;
}

// ---------------------------------------------------------------------------
// K1: sum / sumsq per (tensor,h) segment.  grid (1024, 8), 256 thr, float4
// ---------------------------------------------------------------------------
__global__ void k_reduce(const float* __restrict__ pic, const float* __restrict__ ctx) {
    int seg = blockIdx.y;                       // tensor*4 + h
    const float4* x = (const float4*)((seg >= 4 ? ctx : pic) + (size_t)(seg & 3) * SEG);
    int base = blockIdx.x * 256 + threadIdx.x;  // float4 index, 0..262143 per step
    float s = 0.f, s2 = 0.f;
    #pragma unroll
    for (int k = 0; k < 4; k++) {
        float4 v = x[base + k * 262144];
        s  += (v.x + v.y) + (v.z + v.w);
        s2 += (v.x * v.x + v.y * v.y) + (v.z * v.z + v.w * v.w);
    }
    int lane = threadIdx.x & 31, w = threadIdx.x >> 5;
    s = warp_sum(s); s2 = warp_sum(s2);
    __shared__ float aS[8], aS2[8];
    if (lane == 0) { aS[w] = s; aS2[w] = s2; }
    __syncthreads();
    if (threadIdx.x == 0) {
        float ts = 0.f, ts2 = 0.f;
        #pragma unroll
        for (int i = 0; i < 8; i++) { ts += aS[i]; ts2 += aS2[i]; }
        atomicAdd(&g_sum[seg], (double)ts);
        atomicAdd(&g_sumsq[seg], (double)ts2);
    }
}

// ---------------------------------------------------------------------------
// K2: finalize mean / 1/sqrt(var+eps)
// ---------------------------------------------------------------------------
__global__ void k_stats() {
    int t = threadIdx.x;
    if (t < 8) {
        double cnt = (double)SEG;
        double m = g_sum[t] / cnt;
        double v = g_sumsq[t] / cnt - m * m;
        g_m[t] = (float)m;
        g_rinv[t] = (float)(1.0 / sqrt(v + 1e-5));
    }
}

// ---------------------------------------------------------------------------
// K3: spikes -> packed bits, COALESCED.
//     One block = one DIM-row (8192 elems = 2048 float4). grid (2048, 2), 256 thr.
//     Lane L loads float4 (k*256 + tid): adjacent lanes -> adjacent 16B (4 lines
//     per warp LDG.128 instead of 32). Each 8-lane group assembles one 32-bit
//     word via 3x shfl_xor OR-merge; lane (L&7)==0 stores it.
//     Arithmetic sequence identical to the passing version (bit-exact spikes).
// ---------------------------------------------------------------------------
__global__ void k_spike(const float* __restrict__ pic, const float* __restrict__ ctx,
                        const float* __restrict__ gamma, const float* __restrict__ beta) {
    int tensor = blockIdx.y;
    const float4* x = (const float4*)(tensor ? ctx : pic);
    int tid = threadIdx.x, lane = tid & 31;
    int h = blockIdx.x >> 9;                        // 512 rows per segment
    float m = g_m[tensor * 4 + h];
    float rinv = g_rinv[tensor * 4 + h];
    size_t blockF4 = (size_t)blockIdx.x * 2048;     // float4 base of this row
    unsigned* bitsOut = g_bits[tensor] + blockIdx.x * 256;
    unsigned sh = 4u * (lane & 7);

    #pragma unroll
    for (int k = 0; k < 8; k++) {
        int f = k * 256 + tid;                      // float4 index within row, 0..2047
        float4 v  = x[blockF4 + f];
        float4 ga = *(const float4*)&gamma[f * 4];
        float4 be = *(const float4*)&beta[f * 4];
        float y0 = (v.x - m) * rinv;
        float y1 = (v.y - m) * rinv;
        float y2 = (v.z - m) * rinv;
        float y3 = (v.w - m) * rinv;
        unsigned nib = 0;
        nib |= (__fadd_rn(__fmul_rn(y0, ga.x), be.x) > 1.0f) ? 1u : 0u;
        nib |= (__fadd_rn(__fmul_rn(y1, ga.y), be.y) > 1.0f) ? 2u : 0u;
        nib |= (__fadd_rn(__fmul_rn(y2, ga.z), be.z) > 1.0f) ? 4u : 0u;
        nib |= (__fadd_rn(__fmul_rn(y3, ga.w), be.w) > 1.0f) ? 8u : 0u;
        unsigned word = nib << sh;
        word |= __shfl_xor_sync(0xffffffffu, word, 1);
        word |= __shfl_xor_sync(0xffffffffu, word, 2);
        word |= __shfl_xor_sync(0xffffffffu, word, 4);
        if ((lane & 7) == 0) bitsOut[f >> 3] = word;
    }
}

// ---------------------------------------------------------------------------
// K4: W -> bf16 hi/lo split.  float4 in, packed unsigned out.
//     grid (1024, 2), 256 thr
// ---------------------------------------------------------------------------
__global__ void k_prepW(const float* __restrict__ Wpic, const float* __restrict__ Wctx) {
    int mat = blockIdx.y;
    int i = blockIdx.x * 256 + threadIdx.x;     // float4 index 0..262143
    const float4* W = (const float4*)(mat ? Wctx : Wpic);
    float4 wv = W[i];
    unsigned* Whi32 = (unsigned*)g_Whi[mat];
    unsigned* Wlo32 = (unsigned*)g_Wlo[mat];
    __nv_bfloat16 h0 = __float2bfloat16(wv.x), h1 = __float2bfloat16(wv.y);
    __nv_bfloat16 h2 = __float2bfloat16(wv.z), h3 = __float2bfloat16(wv.w);
    __nv_bfloat16 l0 = __float2bfloat16(wv.x - __bfloat162float(h0));
    __nv_bfloat16 l1 = __float2bfloat16(wv.y - __bfloat162float(h1));
    __nv_bfloat16 l2 = __float2bfloat16(wv.z - __bfloat162float(h2));
    __nv_bfloat16 l3 = __float2bfloat16(wv.w - __bfloat162float(h3));
    unsigned hi01 = (unsigned)*(unsigned short*)&h0 | ((unsigned)*(unsigned short*)&h1 << 16);
    unsigned hi23 = (unsigned)*(unsigned short*)&h2 | ((unsigned)*(unsigned short*)&h3 << 16);
    unsigned lo01 = (unsigned)*(unsigned short*)&l0 | ((unsigned)*(unsigned short*)&l1 << 16);
    unsigned lo23 = (unsigned)*(unsigned short*)&l2 | ((unsigned)*(unsigned short*)&l3 << 16);
    Whi32[i * 2] = hi01; Whi32[i * 2 + 1] = hi23;
    Wlo32[i * 2] = lo01; Wlo32[i * 2 + 1] = lo23;
}

// ---------------------------------------------------------------------------
// K5: GEMM  C[row][o] = sum_d spike[row][d] * W[o][d]
//     A from bits, B = Whi + Wlo (bf16), fp32 accum, mma.sync m16n8k16.
//     BM=64, BN=128, BK=64. grid (32, KSPLIT, 2), 256 thr (8 warps: 4m x 2n)
// ---------------------------------------------------------------------------
__global__ void __launch_bounds__(256) k_gemm() {
    __shared__ __align__(16) __nv_bfloat16 As[64 * 72];
    __shared__ __align__(16) __nv_bfloat16 Bh[128 * 72];
    __shared__ __align__(16) __nv_bfloat16 Bl[128 * 72];

    int tid = threadIdx.x;
    int mt = blockIdx.x, kz = blockIdx.y, mat = blockIdx.z;
    int mbase = mt * 64;
    const unsigned* bits = g_bits[mat];
    const unsigned* Whi32 = (const unsigned*)g_Whi[mat];
    const unsigned* Wlo32 = (const unsigned*)g_Wlo[mat];

    int lane = tid & 31, w = tid >> 5;
    int wm = w >> 1, wn = w & 1;
    int gid = lane >> 2, tig = lane & 3;

    float acc[8][4];
    #pragma unroll
    for (int i = 0; i < 8; i++)
        #pragma unroll
        for (int j = 0; j < 4; j++) acc[i][j] = 0.f;

    int r_fill = tid >> 2, q = tid & 3;

    for (int kb = 0; kb < KPER / 64; kb++) {
        int k0 = kz * KPER + kb * 64;
        // ---- A tile from bits: 64 rows x 64 k, as bf16 0/1 ----
        {
            unsigned word = bits[(mbase + r_fill) * 256 + (k0 >> 5) + (q >> 1)];
            unsigned b16 = (word >> (16 * (q & 1))) & 0xffffu;
            #pragma unroll
            for (int j = 0; j < 8; j++) {
                unsigned lo = ((b16 >> (2 * j)) & 1u) ? 0x3F80u : 0u;
                unsigned hi = ((b16 >> (2 * j + 1)) & 1u) ? 0x3F80u : 0u;
                *(unsigned*)&As[r_fill * 72 + q * 16 + 2 * j] = lo | (hi << 16);
            }
        }
        // ---- B tiles (hi & lo): 128 n-rows x 64 k ----
        #pragma unroll
        for (int i = 0; i < 16; i++) {
            int l = i * 256 + tid;
            int o = l >> 5, du = l & 31;
            *(unsigned*)&Bh[o * 72 + du * 2] = Whi32[o * 4096 + (k0 >> 1) + du];
            *(unsigned*)&Bl[o * 72 + du * 2] = Wlo32[o * 4096 + (k0 >> 1) + du];
        }
        __syncthreads();

        #pragma unroll
        for (int ks = 0; ks < 64; ks += 16) {
            int r0 = wm * 16 + gid;
            int c  = ks + tig * 2;
            unsigned a0 = *(const unsigned*)&As[r0 * 72 + c];
            unsigned a1 = *(const unsigned*)&As[(r0 + 8) * 72 + c];
            unsigned a2 = *(const unsigned*)&As[r0 * 72 + c + 8];
            unsigned a3 = *(const unsigned*)&As[(r0 + 8) * 72 + c + 8];
            #pragma unroll
            for (int nt = 0; nt < 8; nt++) {
                int nb = (wn * 64 + nt * 8 + gid) * 72;
                unsigned b0 = *(const unsigned*)&Bh[nb + c];
                unsigned b1 = *(const unsigned*)&Bh[nb + c + 8];
                asm volatile(
                    "mma.sync.aligned.m16n8k16.row.col.f32.bf16.bf16.f32 "
                    "{%0,%1,%2,%3}, {%4,%5,%6,%7}, {%8,%9}, {%0,%1,%2,%3};\n"
                    : "+f"(acc[nt][0]), "+f"(acc[nt][1]), "+f"(acc[nt][2]), "+f"(acc[nt][3])
                    : "r"(a0), "r"(a1), "r"(a2), "r"(a3), "r"(b0), "r"(b1));
                unsigned d0 = *(const unsigned*)&Bl[nb + c];
                unsigned d1 = *(const unsigned*)&Bl[nb + c + 8];
                asm volatile(
                    "mma.sync.aligned.m16n8k16.row.col.f32.bf16.bf16.f32 "
                    "{%0,%1,%2,%3}, {%4,%5,%6,%7}, {%8,%9}, {%0,%1,%2,%3};\n"
                    : "+f"(acc[nt][0]), "+f"(acc[nt][1]), "+f"(acc[nt][2]), "+f"(acc[nt][3])
                    : "r"(a0), "r"(a1), "r"(a2), "r"(a3), "r"(d0), "r"(d1));
            }
        }
        __syncthreads();
    }

    // ---- store split-K partials ----
    int part = mat * KSPLIT + kz;
    #pragma unroll
    for (int nt = 0; nt < 8; nt++) {
        int col = wn * 64 + nt * 8 + tig * 2;
        int row0 = mbase + wm * 16 + gid;
        size_t i0 = ((size_t)(part * ROWS + row0)) * NOUT + col;
        g_Cpart[i0]     = acc[nt][0];
        g_Cpart[i0 + 1] = acc[nt][1];
        size_t i1 = i0 + (size_t)8 * NOUT;
        g_Cpart[i1]     = acc[nt][2];
        g_Cpart[i1 + 1] = acc[nt][3];
    }
}

// ---------------------------------------------------------------------------
// K6: per-row epilogue: bias, scale, s_ic/s_V, softmax, out2 / ic / ip_sum.
//     grid 2048 blocks (row = h*512+n), 128 thr (o)
// ---------------------------------------------------------------------------
__global__ void k_epilogue(const float* __restrict__ b_pic, const float* __restrict__ b_ctx) {
    int row = blockIdx.x;
    int o = threadIdx.x;
    int lane = o & 31, w = o >> 5;

    float ipv = b_pic[o];
    #pragma unroll
    for (int s = 0; s < KSPLIT; s++)
        ipv += g_Cpart[((size_t)(s * ROWS + row)) * NOUT + o];
    ipv *= 0.125f;                                  // SCALE = 64^-0.5

    float ctxv = b_ctx[o];
    #pragma unroll
    for (int s = 0; s < KSPLIT; s++)
        ctxv += g_Cpart[((size_t)((KSPLIT + s) * ROWS + row)) * NOUT + o];

    __shared__ float sA[4], sB[4], sM[4], sZ[4];
    float cs = warp_sum(ctxv);
    float is = warp_sum(ipv);
    if (lane == 0) { sA[w] = cs; sB[w] = is; }
    __syncthreads();
    float s_ic = sA[0] + sA[1];                     // o < 64  -> warps 0,1
    float s_V  = sA[2] + sA[3];                     // o >= 64 -> warps 2,3
    float ipsum = sB[0] + sB[1] + sB[2] + sB[3];

    float sim = ipv * s_ic;
    float mw = warp_max(sim);
    if (lane == 0) sM[w] = mw;
    __syncthreads();
    float mx = fmaxf(fmaxf(sM[0], sM[1]), fmaxf(sM[2], sM[3]));
    float e = expf(sim - mx);
    float zw = warp_sum(e);
    if (lane == 0) sZ[w] = zw;
    __syncthreads();
    float Z = sZ[0] + sZ[1] + sZ[2] + sZ[3];
    float outv = (e / Z) * s_V;

    int h = row >> 9, n = row & 511;
    g_out2[n * 512 + h * 128 + o] = outv;
    if (o < 64) g_ic[row * 64 + o] = ctxv;
    if (o == 0) g_ipsum[row] = ipsum;
}

// ---------------------------------------------------------------------------
// K7: fuse conv1 (32x512) and conv2 (1x32) into a single 512-vector
// ---------------------------------------------------------------------------
__global__ void k_head1(const float* __restrict__ c1w, const float* __restrict__ c1b,
                        const float* __restrict__ c2w, const float* __restrict__ c2b) {
    int c = threadIdx.x;                // 512 threads
    float acc = 0.f;
    #pragma unroll
    for (int o = 0; o < 32; o++) acc += c2w[o] * c1w[o * 512 + c];
    g_weff[c] = acc;
    if (c == 0) {
        float b = 0.f;
        #pragma unroll
        for (int o = 0; o < 32; o++) b += c2w[o] * c1b[o];
        g_beff = b + c2b[0];
    }
}

// K8: o2[l] = sum_c w_eff[c]*out2[c][l] + b_eff.  grid 2 x 256 thr
__global__ void k_head2() {
    int l = blockIdx.x * 256 + threadIdx.x;
    float acc = g_beff;
    for (int c = 0; c < 512; c++) acc += g_weff[c] * g_out2[c * 512 + l];
    g_o2[l] = acc;
}

// K9: o3[j] = o2 . fc_w[j,:] + fc_b[j].  grid 512 blocks x 128 thr
__global__ void k_head3(const float* __restrict__ fcw, const float* __restrict__ fcb) {
    int j = blockIdx.x;
    int t = threadIdx.x, lane = t & 31, w = t >> 5;
    float p = 0.f;
    for (int l = t; l < 512; l += 128) p += g_o2[l] * fcw[j * 512 + l];
    p = warp_sum(p);
    __shared__ float sP[4];
    if (lane == 0) sP[w] = p;
    __syncthreads();
    if (t == 0) g_o3[j] = sP[0] + sP[1] + sP[2] + sP[3] + fcb[j];
}

// ---------------------------------------------------------------------------
// K10: final — broadcast add, transpose, 4->64 linear interp, relus + ic_sum
//      grid 512 blocks (n) x 64 thr (j)
// ---------------------------------------------------------------------------
__global__ void k_final(float* __restrict__ out) {
    int n = blockIdx.x, j = threadIdx.x;
    float o3n = g_o3[n];
    float tv[4];
    #pragma unroll
    for (int h = 0; h < 4; h++) tv[h] = o3n + g_ipsum[h * 512 + n];
    float src = fmaxf((j + 0.5f) * 0.0625f - 0.5f, 0.0f);
    int i0 = (int)floorf(src); if (i0 > 3) i0 = 3;
    int i1 = i0 + 1; if (i1 > 3) i1 = 3;
    float wgt = src - (float)i0;
    float val = tv[i0] * (1.0f - wgt) + tv[i1] * wgt;
    val = fmaxf(val, 0.0f);
    float ics = 0.f;
    #pragma unroll
    for (int h = 0; h < 4; h++) ics += g_ic[(h * 512 + n) * 64 + j];
    out[n * 64 + j] = fmaxf(val + ics, 0.0f);
}

// ---------------------------------------------------------------------------
// Launch
// ---------------------------------------------------------------------------
extern "C" void kernel_launch(void* const* d_in, const int* in_sizes, int n_in,
                              void* d_out, int out_size) {
    const float* pic    = (const float*)d_in[0];
    const float* ctx    = (const float*)d_in[1];
    const float* gamma  = (const float*)d_in[2];
    const float* lnbeta = (const float*)d_in[3];
    const float* Wpic   = (const float*)d_in[4];
    const float* bpic   = (const float*)d_in[5];
    const float* Wctx   = (const float*)d_in[6];
    const float* bctx   = (const float*)d_in[7];
    const float* c1w    = (const float*)d_in[8];
    const float* c1b    = (const float*)d_in[9];
    const float* c2w    = (const float*)d_in[10];
    const float* c2b    = (const float*)d_in[11];
    const float* fcw    = (const float*)d_in[12];
    const float* fcb    = (const float*)d_in[13];
    float* out = (float*)d_out;

    k_zero<<<1, 32>>>();
    k_reduce<<<dim3(1024, 8), 256>>>(pic, ctx);
    k_stats<<<1, 32>>>();
    k_spike<<<dim3(2048, 2), 256>>>(pic, ctx, gamma, lnbeta);
    k_prepW<<<dim3(1024, 2), 256>>>(Wpic, Wctx);
    k_gemm<<<dim3(32, KSPLIT, 2), 256>>>();
    k_epilogue<<<ROWS, 128>>>(bpic, bctx);
    k_head1<<<1, 512>>>(c1w, c1b, c2w, c2b);
    k_head2<<<2, 256>>>();
    k_head3<<<512, 128>>>(fcw, fcb);
    k_final<<<512, 64>>>(out);
}

// round 9
// speedup vs baseline: 1.5383x; 1.1545x over previous
#include <cuda_runtime.h>
#include <cuda_bf16.h>
#include <math.h>

// ---------------------------------------------------------------------------
// Problem constants
// ---------------------------------------------------------------------------
#define H4      4
#define NN      512
#define DIMD    8192
#define ROWS    2048          // H4*NN
#define SEG     4194304       // NN*DIMD elements per (tensor,h)
#define NOUT    128           // inner = heads*dh
#define KSPLIT  8
#define KPER    1024          // 8192 / KSPLIT
#define GEMM_SMEM 55296       // As 18432 + Bh 18432 + Bl 18432

// ---------------------------------------------------------------------------
// Device scratch (static allocations only — no cudaMalloc allowed)
// ---------------------------------------------------------------------------
__device__ double g_sum[8];
__device__ double g_sumsq[8];
__device__ float  g_m[8];
__device__ float  g_rinv[8];
__device__ unsigned g_bits[2][ROWS * 256];                 // 4 MB, spike bitmasks
__device__ __nv_bfloat16 g_Whi[2][DIMD * NOUT];            // W hi, layout [o][d]
__device__ __nv_bfloat16 g_Wlo[2][DIMD * NOUT];            // W lo
__device__ float g_Cpart[2 * KSPLIT * ROWS * NOUT];        // 16 MB split-K partials
__device__ float g_out2[NN * 512];                         // (n, h*128+o)
__device__ float g_ic[ROWS * 64];                          // ic values per row
__device__ float g_ipsum[ROWS];
__device__ float g_weff[NN];
__device__ float g_beff;
__device__ float g_o2[NN];
__device__ float g_o3[NN];

// ---------------------------------------------------------------------------
// Helpers
// ---------------------------------------------------------------------------
__device__ __forceinline__ float warp_sum(float v) {
    #pragma unroll
    for (int o = 16; o; o >>= 1) v += __shfl_xor_sync(0xffffffffu, v, o);
    return v;
}
__device__ __forceinline__ float warp_max(float v) {
    #pragma unroll
    for (int o = 16; o; o >>= 1) v = fmaxf(v, __shfl_xor_sync(0xffffffffu, v, o));
    return v;
}

// ---------------------------------------------------------------------------
// K0: zero the double accumulators (graph replays must be deterministic)
// ---------------------------------------------------------------------------
__global__ void k_zero() {
    int t = threadIdx.x;
    if (t < 8) g_sum[t] = 0.0;
    else if (t < 16) g_sumsq[t - 8] = 0.0;
}

// ---------------------------------------------------------------------------
// K1: sum / sumsq per (tensor,h) segment.  grid (1024, 8), 256 thr, float4
// ---------------------------------------------------------------------------
__global__ void k_reduce(const float* __restrict__ pic, const float* __restrict__ ctx) {
    int seg = blockIdx.y;                       // tensor*4 + h
    const float4* x = (const float4*)((seg >= 4 ? ctx : pic) + (size_t)(seg & 3) * SEG);
    int base = blockIdx.x * 256 + threadIdx.x;  // float4 index, 0..262143 per step
    float s = 0.f, s2 = 0.f;
    #pragma unroll
    for (int k = 0; k < 4; k++) {
        float4 v = x[base + k * 262144];
        s  += (v.x + v.y) + (v.z + v.w);
        s2 += (v.x * v.x + v.y * v.y) + (v.z * v.z + v.w * v.w);
    }
    int lane = threadIdx.x & 31, w = threadIdx.x >> 5;
    s = warp_sum(s); s2 = warp_sum(s2);
    __shared__ float aS[8], aS2[8];
    if (lane == 0) { aS[w] = s; aS2[w] = s2; }
    __syncthreads();
    if (threadIdx.x == 0) {
        float ts = 0.f, ts2 = 0.f;
        #pragma unroll
        for (int i = 0; i < 8; i++) { ts += aS[i]; ts2 += aS2[i]; }
        atomicAdd(&g_sum[seg], (double)ts);
        atomicAdd(&g_sumsq[seg], (double)ts2);
    }
}

// ---------------------------------------------------------------------------
// K2: finalize mean / 1/sqrt(var+eps)
// ---------------------------------------------------------------------------
__global__ void k_stats() {
    int t = threadIdx.x;
    if (t < 8) {
        double cnt = (double)SEG;
        double m = g_sum[t] / cnt;
        double v = g_sumsq[t] / cnt - m * m;
        g_m[t] = (float)m;
        g_rinv[t] = (float)(1.0 / sqrt(v + 1e-5));
    }
}

// ---------------------------------------------------------------------------
// K3: spikes -> packed bits, COALESCED.
//     One block = one DIM-row (8192 elems = 2048 float4). grid (2048, 2), 256 thr.
//     Each 8-lane group assembles one 32-bit word via 3x shfl_xor OR-merge.
//     Arithmetic sequence identical to the passing version (bit-exact spikes).
// ---------------------------------------------------------------------------
__global__ void k_spike(const float* __restrict__ pic, const float* __restrict__ ctx,
                        const float* __restrict__ gamma, const float* __restrict__ beta) {
    int tensor = blockIdx.y;
    const float4* x = (const float4*)(tensor ? ctx : pic);
    int tid = threadIdx.x, lane = tid & 31;
    int h = blockIdx.x >> 9;                        // 512 rows per segment
    float m = g_m[tensor * 4 + h];
    float rinv = g_rinv[tensor * 4 + h];
    size_t blockF4 = (size_t)blockIdx.x * 2048;     // float4 base of this row
    unsigned* bitsOut = g_bits[tensor] + blockIdx.x * 256;
    unsigned sh = 4u * (lane & 7);

    #pragma unroll
    for (int k = 0; k < 8; k++) {
        int f = k * 256 + tid;                      // float4 index within row, 0..2047
        float4 v  = x[blockF4 + f];
        float4 ga = *(const float4*)&gamma[f * 4];
        float4 be = *(const float4*)&beta[f * 4];
        float y0 = (v.x - m) * rinv;
        float y1 = (v.y - m) * rinv;
        float y2 = (v.z - m) * rinv;
        float y3 = (v.w - m) * rinv;
        unsigned nib = 0;
        nib |= (__fadd_rn(__fmul_rn(y0, ga.x), be.x) > 1.0f) ? 1u : 0u;
        nib |= (__fadd_rn(__fmul_rn(y1, ga.y), be.y) > 1.0f) ? 2u : 0u;
        nib |= (__fadd_rn(__fmul_rn(y2, ga.z), be.z) > 1.0f) ? 4u : 0u;
        nib |= (__fadd_rn(__fmul_rn(y3, ga.w), be.w) > 1.0f) ? 8u : 0u;
        unsigned word = nib << sh;
        word |= __shfl_xor_sync(0xffffffffu, word, 1);
        word |= __shfl_xor_sync(0xffffffffu, word, 2);
        word |= __shfl_xor_sync(0xffffffffu, word, 4);
        if ((lane & 7) == 0) bitsOut[f >> 3] = word;
    }
}

// ---------------------------------------------------------------------------
// K4: W -> bf16 hi/lo split.  float4 in, packed unsigned out.
//     grid (1024, 2), 256 thr
// ---------------------------------------------------------------------------
__global__ void k_prepW(const float* __restrict__ Wpic, const float* __restrict__ Wctx) {
    int mat = blockIdx.y;
    int i = blockIdx.x * 256 + threadIdx.x;     // float4 index 0..262143
    const float4* W = (const float4*)(mat ? Wctx : Wpic);
    float4 wv = W[i];
    unsigned* Whi32 = (unsigned*)g_Whi[mat];
    unsigned* Wlo32 = (unsigned*)g_Wlo[mat];
    __nv_bfloat16 h0 = __float2bfloat16(wv.x), h1 = __float2bfloat16(wv.y);
    __nv_bfloat16 h2 = __float2bfloat16(wv.z), h3 = __float2bfloat16(wv.w);
    __nv_bfloat16 l0 = __float2bfloat16(wv.x - __bfloat162float(h0));
    __nv_bfloat16 l1 = __float2bfloat16(wv.y - __bfloat162float(h1));
    __nv_bfloat16 l2 = __float2bfloat16(wv.z - __bfloat162float(h2));
    __nv_bfloat16 l3 = __float2bfloat16(wv.w - __bfloat162float(h3));
    unsigned hi01 = (unsigned)*(unsigned short*)&h0 | ((unsigned)*(unsigned short*)&h1 << 16);
    unsigned hi23 = (unsigned)*(unsigned short*)&h2 | ((unsigned)*(unsigned short*)&h3 << 16);
    unsigned lo01 = (unsigned)*(unsigned short*)&l0 | ((unsigned)*(unsigned short*)&l1 << 16);
    unsigned lo23 = (unsigned)*(unsigned short*)&l2 | ((unsigned)*(unsigned short*)&l3 << 16);
    Whi32[i * 2] = hi01; Whi32[i * 2 + 1] = hi23;
    Wlo32[i * 2] = lo01; Wlo32[i * 2 + 1] = lo23;
}

// ---------------------------------------------------------------------------
// K5: GEMM  C[row][o] = sum_d spike[row][d] * W[o][d]
//     A from bits, B = Whi + Wlo (bf16), fp32 accum, mma.sync m16n8k16.
//     BM=128, BN=128, BK=64.  grid (16, KSPLIT, 2), 256 thr (8 warps: 4m x 2n),
//     each warp owns TWO m16 tiles (mi loop).  Dynamic smem (54 KB).
// ---------------------------------------------------------------------------
__global__ void __launch_bounds__(256) k_gemm() {
    extern __shared__ __align__(16) char smraw[];
    __nv_bfloat16* As = (__nv_bfloat16*)smraw;                 // 128 x 72
    __nv_bfloat16* Bh = (__nv_bfloat16*)(smraw + 18432);       // 128 x 72
    __nv_bfloat16* Bl = (__nv_bfloat16*)(smraw + 36864);       // 128 x 72

    int tid = threadIdx.x;
    int mt = blockIdx.x, kz = blockIdx.y, mat = blockIdx.z;
    int mbase = mt * 128;
    const unsigned* bits = g_bits[mat];
    const unsigned* Whi32 = (const unsigned*)g_Whi[mat];
    const unsigned* Wlo32 = (const unsigned*)g_Wlo[mat];

    int lane = tid & 31, w = tid >> 5;
    int wm = w >> 1, wn = w & 1;
    int gid = lane >> 2, tig = lane & 3;

    float acc[2][8][4];
    #pragma unroll
    for (int mi = 0; mi < 2; mi++)
        #pragma unroll
        for (int i = 0; i < 8; i++)
            #pragma unroll
            for (int j = 0; j < 4; j++) acc[mi][i][j] = 0.f;

    int r_fill = tid >> 1, q = tid & 1;     // 2 threads per row, one 32-bit word each

    for (int kb = 0; kb < KPER / 64; kb++) {
        int k0 = kz * KPER + kb * 64;
        // ---- A tile from bits: 128 rows x 64 k, as bf16 0/1 (STS.128 packed) ----
        {
            unsigned word = bits[(mbase + r_fill) * 256 + (k0 >> 5) + q];
            #pragma unroll
            for (int jj = 0; jj < 4; jj++) {
                uint4 pk;
                unsigned b0 = (word >> (8 * jj)) & 0xffu;
                pk.x = ((b0 & 1u) ? 0x3F80u : 0u) | ((b0 & 2u) ? 0x3F800000u : 0u);
                pk.y = ((b0 & 4u) ? 0x3F80u : 0u) | ((b0 & 8u) ? 0x3F800000u : 0u);
                pk.z = ((b0 & 16u) ? 0x3F80u : 0u) | ((b0 & 32u) ? 0x3F800000u : 0u);
                pk.w = ((b0 & 64u) ? 0x3F80u : 0u) | ((b0 & 128u) ? 0x3F800000u : 0u);
                *(uint4*)&As[r_fill * 72 + q * 32 + jj * 8] = pk;
            }
        }
        // ---- B tiles (hi & lo): 128 n-rows x 64 k ----
        #pragma unroll
        for (int i = 0; i < 16; i++) {
            int l = i * 256 + tid;
            int o = l >> 5, du = l & 31;
            *(unsigned*)&Bh[o * 72 + du * 2] = Whi32[o * 4096 + (k0 >> 1) + du];
            *(unsigned*)&Bl[o * 72 + du * 2] = Wlo32[o * 4096 + (k0 >> 1) + du];
        }
        __syncthreads();

        #pragma unroll
        for (int ks = 0; ks < 64; ks += 16) {
            int c = ks + tig * 2;
            unsigned af[2][4];
            #pragma unroll
            for (int mi = 0; mi < 2; mi++) {
                int r0 = wm * 32 + mi * 16 + gid;
                af[mi][0] = *(const unsigned*)&As[r0 * 72 + c];
                af[mi][1] = *(const unsigned*)&As[(r0 + 8) * 72 + c];
                af[mi][2] = *(const unsigned*)&As[r0 * 72 + c + 8];
                af[mi][3] = *(const unsigned*)&As[(r0 + 8) * 72 + c + 8];
            }
            #pragma unroll
            for (int nt = 0; nt < 8; nt++) {
                int nb = (wn * 64 + nt * 8 + gid) * 72;
                unsigned b0 = *(const unsigned*)&Bh[nb + c];
                unsigned b1 = *(const unsigned*)&Bh[nb + c + 8];
                unsigned d0 = *(const unsigned*)&Bl[nb + c];
                unsigned d1 = *(const unsigned*)&Bl[nb + c + 8];
                #pragma unroll
                for (int mi = 0; mi < 2; mi++) {
                    asm volatile(
                        "mma.sync.aligned.m16n8k16.row.col.f32.bf16.bf16.f32 "
                        "{%0,%1,%2,%3}, {%4,%5,%6,%7}, {%8,%9}, {%0,%1,%2,%3};\n"
                        : "+f"(acc[mi][nt][0]), "+f"(acc[mi][nt][1]),
                          "+f"(acc[mi][nt][2]), "+f"(acc[mi][nt][3])
                        : "r"(af[mi][0]), "r"(af[mi][1]), "r"(af[mi][2]), "r"(af[mi][3]),
                          "r"(b0), "r"(b1));
                    asm volatile(
                        "mma.sync.aligned.m16n8k16.row.col.f32.bf16.bf16.f32 "
                        "{%0,%1,%2,%3}, {%4,%5,%6,%7}, {%8,%9}, {%0,%1,%2,%3};\n"
                        : "+f"(acc[mi][nt][0]), "+f"(acc[mi][nt][1]),
                          "+f"(acc[mi][nt][2]), "+f"(acc[mi][nt][3])
                        : "r"(af[mi][0]), "r"(af[mi][1]), "r"(af[mi][2]), "r"(af[mi][3]),
                          "r"(d0), "r"(d1));
                }
            }
        }
        __syncthreads();
    }

    // ---- store split-K partials ----
    int part = mat * KSPLIT + kz;
    #pragma unroll
    for (int mi = 0; mi < 2; mi++) {
        #pragma unroll
        for (int nt = 0; nt < 8; nt++) {
            int col = wn * 64 + nt * 8 + tig * 2;
            int row0 = mbase + wm * 32 + mi * 16 + gid;
            size_t i0 = ((size_t)(part * ROWS + row0)) * NOUT + col;
            g_Cpart[i0]     = acc[mi][nt][0];
            g_Cpart[i0 + 1] = acc[mi][nt][1];
            size_t i1 = i0 + (size_t)8 * NOUT;
            g_Cpart[i1]     = acc[mi][nt][2];
            g_Cpart[i1 + 1] = acc[mi][nt][3];
        }
    }
}

// ---------------------------------------------------------------------------
// K6: per-row epilogue: bias, scale, s_ic/s_V, softmax, out2 / ic / ip_sum.
//     grid 2048 blocks (row = h*512+n), 128 thr (o)
// ---------------------------------------------------------------------------
__global__ void k_epilogue(const float* __restrict__ b_pic, const float* __restrict__ b_ctx) {
    int row = blockIdx.x;
    int o = threadIdx.x;
    int lane = o & 31, w = o >> 5;

    float ipv = b_pic[o];
    #pragma unroll
    for (int s = 0; s < KSPLIT; s++)
        ipv += g_Cpart[((size_t)(s * ROWS + row)) * NOUT + o];
    ipv *= 0.125f;                                  // SCALE = 64^-0.5

    float ctxv = b_ctx[o];
    #pragma unroll
    for (int s = 0; s < KSPLIT; s++)
        ctxv += g_Cpart[((size_t)((KSPLIT + s) * ROWS + row)) * NOUT + o];

    __shared__ float sA[4], sB[4], sM[4], sZ[4];
    float cs = warp_sum(ctxv);
    float is = warp_sum(ipv);
    if (lane == 0) { sA[w] = cs; sB[w] = is; }
    __syncthreads();
    float s_ic = sA[0] + sA[1];                     // o < 64  -> warps 0,1
    float s_V  = sA[2] + sA[3];                     // o >= 64 -> warps 2,3
    float ipsum = sB[0] + sB[1] + sB[2] + sB[3];

    float sim = ipv * s_ic;
    float mw = warp_max(sim);
    if (lane == 0) sM[w] = mw;
    __syncthreads();
    float mx = fmaxf(fmaxf(sM[0], sM[1]), fmaxf(sM[2], sM[3]));
    float e = expf(sim - mx);
    float zw = warp_sum(e);
    if (lane == 0) sZ[w] = zw;
    __syncthreads();
    float Z = sZ[0] + sZ[1] + sZ[2] + sZ[3];
    float outv = (e / Z) * s_V;

    int h = row >> 9, n = row & 511;
    g_out2[n * 512 + h * 128 + o] = outv;
    if (o < 64) g_ic[row * 64 + o] = ctxv;
    if (o == 0) g_ipsum[row] = ipsum;
}

// ---------------------------------------------------------------------------
// K7: fuse conv1 (32x512) and conv2 (1x32) into a single 512-vector
// ---------------------------------------------------------------------------
__global__ void k_head1(const float* __restrict__ c1w, const float* __restrict__ c1b,
                        const float* __restrict__ c2w, const float* __restrict__ c2b) {
    int c = threadIdx.x;                // 512 threads
    float acc = 0.f;
    #pragma unroll
    for (int o = 0; o < 32; o++) acc += c2w[o] * c1w[o * 512 + c];
    g_weff[c] = acc;
    if (c == 0) {
        float b = 0.f;
        #pragma unroll
        for (int o = 0; o < 32; o++) b += c2w[o] * c1b[o];
        g_beff = b + c2b[0];
    }
}

// K8: o2[l] = sum_c w_eff[c]*out2[c][l] + b_eff.  grid 2 x 256 thr
__global__ void k_head2() {
    int l = blockIdx.x * 256 + threadIdx.x;
    float acc = g_beff;
    for (int c = 0; c < 512; c++) acc += g_weff[c] * g_out2[c * 512 + l];
    g_o2[l] = acc;
}

// K9: o3[j] = o2 . fc_w[j,:] + fc_b[j].  grid 512 blocks x 128 thr
__global__ void k_head3(const float* __restrict__ fcw, const float* __restrict__ fcb) {
    int j = blockIdx.x;
    int t = threadIdx.x, lane = t & 31, w = t >> 5;
    float p = 0.f;
    for (int l = t; l < 512; l += 128) p += g_o2[l] * fcw[j * 512 + l];
    p = warp_sum(p);
    __shared__ float sP[4];
    if (lane == 0) sP[w] = p;
    __syncthreads();
    if (t == 0) g_o3[j] = sP[0] + sP[1] + sP[2] + sP[3] + fcb[j];
}

// ---------------------------------------------------------------------------
// K10: final — broadcast add, transpose, 4->64 linear interp, relus + ic_sum
//      grid 512 blocks (n) x 64 thr (j)
// ---------------------------------------------------------------------------
__global__ void k_final(float* __restrict__ out) {
    int n = blockIdx.x, j = threadIdx.x;
    float o3n = g_o3[n];
    float tv[4];
    #pragma unroll
    for (int h = 0; h < 4; h++) tv[h] = o3n + g_ipsum[h * 512 + n];
    float src = fmaxf((j + 0.5f) * 0.0625f - 0.5f, 0.0f);
    int i0 = (int)floorf(src); if (i0 > 3) i0 = 3;
    int i1 = i0 + 1; if (i1 > 3) i1 = 3;
    float wgt = src - (float)i0;
    float val = tv[i0] * (1.0f - wgt) + tv[i1] * wgt;
    val = fmaxf(val, 0.0f);
    float ics = 0.f;
    #pragma unroll
    for (int h = 0; h < 4; h++) ics += g_ic[(h * 512 + n) * 64 + j];
    out[n * 64 + j] = fmaxf(val + ics, 0.0f);
}

// ---------------------------------------------------------------------------
// Launch
// ---------------------------------------------------------------------------
extern "C" void kernel_launch(void* const* d_in, const int* in_sizes, int n_in,
                              void* d_out, int out_size) {
    const float* pic    = (const float*)d_in[0];
    const float* ctx    = (const float*)d_in[1];
    const float* gamma  = (const float*)d_in[2];
    const float* lnbeta = (const float*)d_in[3];
    const float* Wpic   = (const float*)d_in[4];
    const float* bpic   = (const float*)d_in[5];
    const float* Wctx   = (const float*)d_in[6];
    const float* bctx   = (const float*)d_in[7];
    const float* c1w    = (const float*)d_in[8];
    const float* c1b    = (const float*)d_in[9];
    const float* c2w    = (const float*)d_in[10];
    const float* c2b    = (const float*)d_in[11];
    const float* fcw    = (const float*)d_in[12];
    const float* fcb    = (const float*)d_in[13];
    float* out = (float*)d_out;

    cudaFuncSetAttribute(k_gemm, cudaFuncAttributeMaxDynamicSharedMemorySize, GEMM_SMEM);

    k_zero<<<1, 32>>>();
    k_reduce<<<dim3(1024, 8), 256>>>(pic, ctx);
    k_stats<<<1, 32>>>();
    k_spike<<<dim3(2048, 2), 256>>>(pic, ctx, gamma, lnbeta);
    k_prepW<<<dim3(1024, 2), 256>>>(Wpic, Wctx);
    k_gemm<<<dim3(16, KSPLIT, 2), 256, GEMM_SMEM>>>();
    k_epilogue<<<ROWS, 128>>>(bpic, bctx);
    k_head1<<<1, 512>>>(c1w, c1b, c2w, c2b);
    k_head2<<<2, 256>>>();
    k_head3<<<512, 128>>>(fcw, fcb);
    k_final<<<512, 64>>>(out);
}

// round 10
// speedup vs baseline: 1.5629x; 1.0160x over previous
#include <cuda_runtime.h>
#include <cuda_bf16.h>
#include <math.h>

// ---------------------------------------------------------------------------
// Problem constants
// ---------------------------------------------------------------------------
#define H4      4
#define NN      512
#define DIMD    8192
#define ROWS    2048          // H4*NN
#define SEG     4194304       // NN*DIMD elements per (tensor,h)
#define NOUT    128           // inner = heads*dh
#define KSPLIT  8
#define KPER    1024          // 8192 / KSPLIT
#define GEMM_SMEM 55296       // As 18432 + Bh 18432 + Bl 18432
#define RBLK    512           // k_reduce blocks per segment

// ---------------------------------------------------------------------------
// Device scratch (static allocations only — no cudaMalloc allowed)
// ---------------------------------------------------------------------------
__device__ float  g_rpartS[8 * RBLK];                      // per-block sums
__device__ float  g_rpartQ[8 * RBLK];                      // per-block sumsq
__device__ float  g_m[8];
__device__ float  g_rinv[8];
__device__ unsigned g_bits[2][ROWS * 256];                 // 4 MB, spike bitmasks
__device__ __nv_bfloat16 g_Whi[2][DIMD * NOUT];            // W hi, layout [o][d]
__device__ __nv_bfloat16 g_Wlo[2][DIMD * NOUT];            // W lo
__device__ float g_Cpart[2 * KSPLIT * ROWS * NOUT];        // 16 MB split-K partials
__device__ float g_out2[NN * 512];                         // (n, h*128+o)
__device__ float g_ic[ROWS * 64];                          // ic values per row
__device__ float g_ipsum[ROWS];
__device__ float g_o2[NN];

// ---------------------------------------------------------------------------
// Helpers
// ---------------------------------------------------------------------------
__device__ __forceinline__ float warp_sum(float v) {
    #pragma unroll
    for (int o = 16; o; o >>= 1) v += __shfl_xor_sync(0xffffffffu, v, o);
    return v;
}
__device__ __forceinline__ double warp_sum_d(double v) {
    #pragma unroll
    for (int o = 16; o; o >>= 1) v += __shfl_xor_sync(0xffffffffu, v, o);
    return v;
}
__device__ __forceinline__ float warp_max(float v) {
    #pragma unroll
    for (int o = 16; o; o >>= 1) v = fmaxf(v, __shfl_xor_sync(0xffffffffu, v, o));
    return v;
}

// ---------------------------------------------------------------------------
// K1: sum / sumsq per (tensor,h) segment -> per-block float partials.
//     grid (RBLK, 8), 256 thr, 8x float4 per thread, front-batched loads.
// ---------------------------------------------------------------------------
__global__ void __launch_bounds__(256) k_reduce(const float* __restrict__ pic,
                                                const float* __restrict__ ctx) {
    int seg = blockIdx.y;                       // tensor*4 + h
    const float4* x = (const float4*)((seg >= 4 ? ctx : pic) + (size_t)(seg & 3) * SEG);
    int base = blockIdx.x * 256 + threadIdx.x;  // 0..131071
    float4 v[8];
    #pragma unroll
    for (int k = 0; k < 8; k++) v[k] = x[base + k * 131072];
    float s = 0.f, s2 = 0.f;
    #pragma unroll
    for (int k = 0; k < 8; k++) {
        s  += (v[k].x + v[k].y) + (v[k].z + v[k].w);
        s2 += (v[k].x * v[k].x + v[k].y * v[k].y) + (v[k].z * v[k].z + v[k].w * v[k].w);
    }
    int lane = threadIdx.x & 31, w = threadIdx.x >> 5;
    s = warp_sum(s); s2 = warp_sum(s2);
    __shared__ float aS[8], aS2[8];
    if (lane == 0) { aS[w] = s; aS2[w] = s2; }
    __syncthreads();
    if (threadIdx.x == 0) {
        float ts = 0.f, ts2 = 0.f;
        #pragma unroll
        for (int i = 0; i < 8; i++) { ts += aS[i]; ts2 += aS2[i]; }
        g_rpartS[seg * RBLK + blockIdx.x] = ts;
        g_rpartQ[seg * RBLK + blockIdx.x] = ts2;
    }
}

// ---------------------------------------------------------------------------
// K2: finalize mean / rinv.  1 block, 256 thr, warp w handles segment w.
//     Double-precision accumulation of float block partials (same precision
//     class as the previous double-atomic scheme).
// ---------------------------------------------------------------------------
__global__ void k_stats() {
    int w = threadIdx.x >> 5, lane = threadIdx.x & 31;
    double s = 0.0, s2 = 0.0;
    for (int i = lane; i < RBLK; i += 32) {
        s  += (double)g_rpartS[w * RBLK + i];
        s2 += (double)g_rpartQ[w * RBLK + i];
    }
    s = warp_sum_d(s); s2 = warp_sum_d(s2);
    if (lane == 0) {
        double cnt = (double)SEG;
        double m = s / cnt;
        double v = s2 / cnt - m * m;
        g_m[w] = (float)m;
        g_rinv[w] = (float)(1.0 / sqrt(v + 1e-5));
    }
}

// ---------------------------------------------------------------------------
// K3: spikes -> packed bits, COALESCED + front-batched loads (MLP=8).
//     One block = one DIM-row. grid (2048, 2), 256 thr.
//     Arithmetic sequence identical to the passing version (bit-exact spikes).
// ---------------------------------------------------------------------------
__global__ void __launch_bounds__(256) k_spike(const float* __restrict__ pic,
                                               const float* __restrict__ ctx,
                                               const float* __restrict__ gamma,
                                               const float* __restrict__ beta) {
    int tensor = blockIdx.y;
    const float4* x = (const float4*)(tensor ? ctx : pic);
    int tid = threadIdx.x, lane = tid & 31;
    int h = blockIdx.x >> 9;                        // 512 rows per segment
    float m = g_m[tensor * 4 + h];
    float rinv = g_rinv[tensor * 4 + h];
    size_t blockF4 = (size_t)blockIdx.x * 2048;     // float4 base of this row
    unsigned* bitsOut = g_bits[tensor] + blockIdx.x * 256;
    unsigned sh = 4u * (lane & 7);

    float4 xv[8];
    #pragma unroll
    for (int k = 0; k < 8; k++) xv[k] = x[blockF4 + k * 256 + tid];

    #pragma unroll
    for (int k = 0; k < 8; k++) {
        int f = k * 256 + tid;
        float4 ga = *(const float4*)&gamma[f * 4];
        float4 be = *(const float4*)&beta[f * 4];
        float y0 = (xv[k].x - m) * rinv;
        float y1 = (xv[k].y - m) * rinv;
        float y2 = (xv[k].z - m) * rinv;
        float y3 = (xv[k].w - m) * rinv;
        unsigned nib = 0;
        nib |= (__fadd_rn(__fmul_rn(y0, ga.x), be.x) > 1.0f) ? 1u : 0u;
        nib |= (__fadd_rn(__fmul_rn(y1, ga.y), be.y) > 1.0f) ? 2u : 0u;
        nib |= (__fadd_rn(__fmul_rn(y2, ga.z), be.z) > 1.0f) ? 4u : 0u;
        nib |= (__fadd_rn(__fmul_rn(y3, ga.w), be.w) > 1.0f) ? 8u : 0u;
        unsigned word = nib << sh;
        word |= __shfl_xor_sync(0xffffffffu, word, 1);
        word |= __shfl_xor_sync(0xffffffffu, word, 2);
        word |= __shfl_xor_sync(0xffffffffu, word, 4);
        if ((lane & 7) == 0) bitsOut[f >> 3] = word;
    }
}

// ---------------------------------------------------------------------------
// K4: W -> bf16 hi/lo split.  float4 in, packed unsigned out.
//     grid (1024, 2), 256 thr
// ---------------------------------------------------------------------------
__global__ void k_prepW(const float* __restrict__ Wpic, const float* __restrict__ Wctx) {
    int mat = blockIdx.y;
    int i = blockIdx.x * 256 + threadIdx.x;     // float4 index 0..262143
    const float4* W = (const float4*)(mat ? Wctx : Wpic);
    float4 wv = W[i];
    unsigned* Whi32 = (unsigned*)g_Whi[mat];
    unsigned* Wlo32 = (unsigned*)g_Wlo[mat];
    __nv_bfloat16 h0 = __float2bfloat16(wv.x), h1 = __float2bfloat16(wv.y);
    __nv_bfloat16 h2 = __float2bfloat16(wv.z), h3 = __float2bfloat16(wv.w);
    __nv_bfloat16 l0 = __float2bfloat16(wv.x - __bfloat162float(h0));
    __nv_bfloat16 l1 = __float2bfloat16(wv.y - __bfloat162float(h1));
    __nv_bfloat16 l2 = __float2bfloat16(wv.z - __bfloat162float(h2));
    __nv_bfloat16 l3 = __float2bfloat16(wv.w - __bfloat162float(h3));
    unsigned hi01 = (unsigned)*(unsigned short*)&h0 | ((unsigned)*(unsigned short*)&h1 << 16);
    unsigned hi23 = (unsigned)*(unsigned short*)&h2 | ((unsigned)*(unsigned short*)&h3 << 16);
    unsigned lo01 = (unsigned)*(unsigned short*)&l0 | ((unsigned)*(unsigned short*)&l1 << 16);
    unsigned lo23 = (unsigned)*(unsigned short*)&l2 | ((unsigned)*(unsigned short*)&l3 << 16);
    Whi32[i * 2] = hi01; Whi32[i * 2 + 1] = hi23;
    Wlo32[i * 2] = lo01; Wlo32[i * 2 + 1] = lo23;
}

// ---------------------------------------------------------------------------
// K5: GEMM  C[row][o] = sum_d spike[row][d] * W[o][d]
//     BM=128, BN=128, BK=64.  grid (16, KSPLIT, 2), 256 thr, dyn smem 54 KB.
// ---------------------------------------------------------------------------
__global__ void __launch_bounds__(256) k_gemm() {
    extern __shared__ __align__(16) char smraw[];
    __nv_bfloat16* As = (__nv_bfloat16*)smraw;                 // 128 x 72
    __nv_bfloat16* Bh = (__nv_bfloat16*)(smraw + 18432);       // 128 x 72
    __nv_bfloat16* Bl = (__nv_bfloat16*)(smraw + 36864);       // 128 x 72

    int tid = threadIdx.x;
    int mt = blockIdx.x, kz = blockIdx.y, mat = blockIdx.z;
    int mbase = mt * 128;
    const unsigned* bits = g_bits[mat];
    const unsigned* Whi32 = (const unsigned*)g_Whi[mat];
    const unsigned* Wlo32 = (const unsigned*)g_Wlo[mat];

    int lane = tid & 31, w = tid >> 5;
    int wm = w >> 1, wn = w & 1;
    int gid = lane >> 2, tig = lane & 3;

    float acc[2][8][4];
    #pragma unroll
    for (int mi = 0; mi < 2; mi++)
        #pragma unroll
        for (int i = 0; i < 8; i++)
            #pragma unroll
            for (int j = 0; j < 4; j++) acc[mi][i][j] = 0.f;

    int r_fill = tid >> 1, q = tid & 1;     // 2 threads per row, one 32-bit word each

    for (int kb = 0; kb < KPER / 64; kb++) {
        int k0 = kz * KPER + kb * 64;
        // ---- A tile from bits: 128 rows x 64 k, as bf16 0/1 (STS.128 packed) ----
        {
            unsigned word = bits[(mbase + r_fill) * 256 + (k0 >> 5) + q];
            #pragma unroll
            for (int jj = 0; jj < 4; jj++) {
                uint4 pk;
                unsigned b0 = (word >> (8 * jj)) & 0xffu;
                pk.x = ((b0 & 1u) ? 0x3F80u : 0u) | ((b0 & 2u) ? 0x3F800000u : 0u);
                pk.y = ((b0 & 4u) ? 0x3F80u : 0u) | ((b0 & 8u) ? 0x3F800000u : 0u);
                pk.z = ((b0 & 16u) ? 0x3F80u : 0u) | ((b0 & 32u) ? 0x3F800000u : 0u);
                pk.w = ((b0 & 64u) ? 0x3F80u : 0u) | ((b0 & 128u) ? 0x3F800000u : 0u);
                *(uint4*)&As[r_fill * 72 + q * 32 + jj * 8] = pk;
            }
        }
        // ---- B tiles (hi & lo): 128 n-rows x 64 k ----
        #pragma unroll
        for (int i = 0; i < 16; i++) {
            int l = i * 256 + tid;
            int o = l >> 5, du = l & 31;
            *(unsigned*)&Bh[o * 72 + du * 2] = Whi32[o * 4096 + (k0 >> 1) + du];
            *(unsigned*)&Bl[o * 72 + du * 2] = Wlo32[o * 4096 + (k0 >> 1) + du];
        }
        __syncthreads();

        #pragma unroll
        for (int ks = 0; ks < 64; ks += 16) {
            int c = ks + tig * 2;
            unsigned af[2][4];
            #pragma unroll
            for (int mi = 0; mi < 2; mi++) {
                int r0 = wm * 32 + mi * 16 + gid;
                af[mi][0] = *(const unsigned*)&As[r0 * 72 + c];
                af[mi][1] = *(const unsigned*)&As[(r0 + 8) * 72 + c];
                af[mi][2] = *(const unsigned*)&As[r0 * 72 + c + 8];
                af[mi][3] = *(const unsigned*)&As[(r0 + 8) * 72 + c + 8];
            }
            #pragma unroll
            for (int nt = 0; nt < 8; nt++) {
                int nb = (wn * 64 + nt * 8 + gid) * 72;
                unsigned b0 = *(const unsigned*)&Bh[nb + c];
                unsigned b1 = *(const unsigned*)&Bh[nb + c + 8];
                unsigned d0 = *(const unsigned*)&Bl[nb + c];
                unsigned d1 = *(const unsigned*)&Bl[nb + c + 8];
                #pragma unroll
                for (int mi = 0; mi < 2; mi++) {
                    asm volatile(
                        "mma.sync.aligned.m16n8k16.row.col.f32.bf16.bf16.f32 "
                        "{%0,%1,%2,%3}, {%4,%5,%6,%7}, {%8,%9}, {%0,%1,%2,%3};\n"
                        : "+f"(acc[mi][nt][0]), "+f"(acc[mi][nt][1]),
                          "+f"(acc[mi][nt][2]), "+f"(acc[mi][nt][3])
                        : "r"(af[mi][0]), "r"(af[mi][1]), "r"(af[mi][2]), "r"(af[mi][3]),
                          "r"(b0), "r"(b1));
                    asm volatile(
                        "mma.sync.aligned.m16n8k16.row.col.f32.bf16.bf16.f32 "
                        "{%0,%1,%2,%3}, {%4,%5,%6,%7}, {%8,%9}, {%0,%1,%2,%3};\n"
                        : "+f"(acc[mi][nt][0]), "+f"(acc[mi][nt][1]),
                          "+f"(acc[mi][nt][2]), "+f"(acc[mi][nt][3])
                        : "r"(af[mi][0]), "r"(af[mi][1]), "r"(af[mi][2]), "r"(af[mi][3]),
                          "r"(d0), "r"(d1));
                }
            }
        }
        __syncthreads();
    }

    // ---- store split-K partials ----
    int part = mat * KSPLIT + kz;
    #pragma unroll
    for (int mi = 0; mi < 2; mi++) {
        #pragma unroll
        for (int nt = 0; nt < 8; nt++) {
            int col = wn * 64 + nt * 8 + tig * 2;
            int row0 = mbase + wm * 32 + mi * 16 + gid;
            size_t i0 = ((size_t)(part * ROWS + row0)) * NOUT + col;
            g_Cpart[i0]     = acc[mi][nt][0];
            g_Cpart[i0 + 1] = acc[mi][nt][1];
            size_t i1 = i0 + (size_t)8 * NOUT;
            g_Cpart[i1]     = acc[mi][nt][2];
            g_Cpart[i1 + 1] = acc[mi][nt][3];
        }
    }
}

// ---------------------------------------------------------------------------
// K6: per-row epilogue: bias, scale, s_ic/s_V, softmax, out2 / ic / ip_sum.
//     grid 2048 blocks (row = h*512+n), 128 thr (o)
// ---------------------------------------------------------------------------
__global__ void k_epilogue(const float* __restrict__ b_pic, const float* __restrict__ b_ctx) {
    int row = blockIdx.x;
    int o = threadIdx.x;
    int lane = o & 31, w = o >> 5;

    float ipv = b_pic[o];
    #pragma unroll
    for (int s = 0; s < KSPLIT; s++)
        ipv += g_Cpart[((size_t)(s * ROWS + row)) * NOUT + o];
    ipv *= 0.125f;                                  // SCALE = 64^-0.5

    float ctxv = b_ctx[o];
    #pragma unroll
    for (int s = 0; s < KSPLIT; s++)
        ctxv += g_Cpart[((size_t)((KSPLIT + s) * ROWS + row)) * NOUT + o];

    __shared__ float sA[4], sB[4], sM[4], sZ[4];
    float cs = warp_sum(ctxv);
    float is = warp_sum(ipv);
    if (lane == 0) { sA[w] = cs; sB[w] = is; }
    __syncthreads();
    float s_ic = sA[0] + sA[1];                     // o < 64  -> warps 0,1
    float s_V  = sA[2] + sA[3];                     // o >= 64 -> warps 2,3
    float ipsum = sB[0] + sB[1] + sB[2] + sB[3];

    float sim = ipv * s_ic;
    float mw = warp_max(sim);
    if (lane == 0) sM[w] = mw;
    __syncthreads();
    float mx = fmaxf(fmaxf(sM[0], sM[1]), fmaxf(sM[2], sM[3]));
    float e = expf(sim - mx);
    float zw = warp_sum(e);
    if (lane == 0) sZ[w] = zw;
    __syncthreads();
    float Z = sZ[0] + sZ[1] + sZ[2] + sZ[3];
    float outv = (e / Z) * s_V;

    int h = row >> 9, n = row & 511;
    g_out2[n * 512 + h * 128 + o] = outv;
    if (o < 64) g_ic[row * 64 + o] = ctxv;
    if (o == 0) g_ipsum[row] = ipsum;
}

// ---------------------------------------------------------------------------
// K7: headA — conv1/conv2 collapse (weff,beff) then o2 = weff·out2 + beff.
//     ONE block, 512 thr.
// ---------------------------------------------------------------------------
__global__ void __launch_bounds__(512) k_headA(const float* __restrict__ c1w,
                                               const float* __restrict__ c1b,
                                               const float* __restrict__ c2w,
                                               const float* __restrict__ c2b) {
    __shared__ float sw[512];
    __shared__ float sbeff;
    int t = threadIdx.x;
    float acc = 0.f;
    #pragma unroll
    for (int o = 0; o < 32; o++) acc += c2w[o] * c1w[o * 512 + t];
    sw[t] = acc;
    if (t == 0) {
        float b = 0.f;
        #pragma unroll
        for (int o = 0; o < 32; o++) b += c2w[o] * c1b[o];
        sbeff = b + c2b[0];
    }
    __syncthreads();
    float a2 = sbeff;
    for (int c = 0; c < 512; c++) a2 += sw[c] * g_out2[c * 512 + t];
    g_o2[t] = a2;
}

// ---------------------------------------------------------------------------
// K8: tail — block j: o3 = o2·fc_w[j,:] + fc_b[j], then the 64 outputs for
//     row n=j (broadcast add, interp 4->64, relus + ic_sum).  grid 512 x 128.
// ---------------------------------------------------------------------------
__global__ void k_tail(const float* __restrict__ fcw, const float* __restrict__ fcb,
                       float* __restrict__ out) {
    int n = blockIdx.x;
    int t = threadIdx.x, lane = t & 31, w = t >> 5;
    float p = 0.f;
    for (int l = t; l < 512; l += 128) p += g_o2[l] * fcw[n * 512 + l];
    p = warp_sum(p);
    __shared__ float sP[4];
    __shared__ float sO3;
    if (lane == 0) sP[w] = p;
    __syncthreads();
    if (t == 0) sO3 = sP[0] + sP[1] + sP[2] + sP[3] + fcb[n];
    __syncthreads();

    if (t < 64) {
        int j = t;
        float o3n = sO3;
        float tv[4];
        #pragma unroll
        for (int h = 0; h < 4; h++) tv[h] = o3n + g_ipsum[h * 512 + n];
        float src = fmaxf((j + 0.5f) * 0.0625f - 0.5f, 0.0f);
        int i0 = (int)floorf(src); if (i0 > 3) i0 = 3;
        int i1 = i0 + 1; if (i1 > 3) i1 = 3;
        float wgt = src - (float)i0;
        float val = tv[i0] * (1.0f - wgt) + tv[i1] * wgt;
        val = fmaxf(val, 0.0f);
        float ics = 0.f;
        #pragma unroll
        for (int h = 0; h < 4; h++) ics += g_ic[(h * 512 + n) * 64 + j];
        out[n * 64 + j] = fmaxf(val + ics, 0.0f);
    }
}

// ---------------------------------------------------------------------------
// Launch
// ---------------------------------------------------------------------------
extern "C" void kernel_launch(void* const* d_in, const int* in_sizes, int n_in,
                              void* d_out, int out_size) {
    const float* pic    = (const float*)d_in[0];
    const float* ctx    = (const float*)d_in[1];
    const float* gamma  = (const float*)d_in[2];
    const float* lnbeta = (const float*)d_in[3];
    const float* Wpic   = (const float*)d_in[4];
    const float* bpic   = (const float*)d_in[5];
    const float* Wctx   = (const float*)d_in[6];
    const float* bctx   = (const float*)d_in[7];
    const float* c1w    = (const float*)d_in[8];
    const float* c1b    = (const float*)d_in[9];
    const float* c2w    = (const float*)d_in[10];
    const float* c2b    = (const float*)d_in[11];
    const float* fcw    = (const float*)d_in[12];
    const float* fcb    = (const float*)d_in[13];
    float* out = (float*)d_out;

    cudaFuncSetAttribute(k_gemm, cudaFuncAttributeMaxDynamicSharedMemorySize, GEMM_SMEM);

    k_reduce<<<dim3(RBLK, 8), 256>>>(pic, ctx);
    k_stats<<<1, 256>>>();
    k_spike<<<dim3(2048, 2), 256>>>(pic, ctx, gamma, lnbeta);
    k_prepW<<<dim3(1024, 2), 256>>>(Wpic, Wctx);
    k_gemm<<<dim3(16, KSPLIT, 2), 256, GEMM_SMEM>>>();
    k_epilogue<<<ROWS, 128>>>(bpic, bctx);
    k_headA<<<1, 512>>>(c1w, c1b, c2w, c2b);
    k_tail<<<512, 128>>>(fcw, fcb, out);
}